// round 12
// baseline (speedup 1.0000x reference)
#include <cuda_runtime.h>
#include <cuda_fp16.h>
#include <math.h>
#include <stdint.h>

// ---------------- problem constants ----------------
constexpr int kNL = 4;
constexpr int kD  = 1024;
constexpr int kD2 = 2048;
constexpr int kH  = 16;
constexpr int kDH = 64;
constexpr int kV  = 32000;
constexpr int kB  = 2;
constexpr int kL  = 2048;
constexpr int kBL = kB * kL;   // 4096
constexpr int kQS = 3 * kD;    // fused qkv row stride (3072)
constexpr int kPU = 2 * kD2;   // fused proj/up row stride (4096)
#define EPSF 1e-6f

// ---------------- scratch (device globals; no allocation allowed) ----------------
__device__ __align__(1024) float  g_x[kBL * kD];                  // residual (fp32)
__device__ __align__(1024) __half g_qkv[(size_t)kBL * kQS];       // fused q|k|v (fp16)
__device__ __align__(1024) __half g_pu[(size_t)kBL * kPU];        // fused proj|up (fp16)
__device__ __align__(1024) __half g_h[kBL * kD];                  // rmsnorm out / logits A
__device__ __align__(1024) __half g_att[kBL * kD];                // attention out
__device__ __align__(1024) __half g_gate[(size_t)kBL * kD2];      // silu out
__device__ __align__(1024) float  g_bqkv[kNL * kQS];              // fused qkv bias
__device__ __align__(1024) float  g_bpu[kNL * kPU];               // fused proj/up bias

// fp16 + TRANSPOSED weights, [N][K] blocks. Per-layer fused layouts.
constexpr size_t kDD = (size_t)kD * kD;                 // 1M
__device__ __forceinline__ __host__ size_t qkvOff(int i) { return (size_t)i * 3 * kDD; }
constexpr size_t kWoBase = (size_t)kNL * 3 * kDD;       // 12M
__device__ __forceinline__ __host__ size_t woOff(int i)  { return kWoBase + (size_t)i * kDD; }
constexpr size_t kPuBase = kWoBase + (size_t)kNL * kDD; // 16M
__device__ __forceinline__ __host__ size_t puOff(int i)  { return kPuBase + (size_t)i * 4 * kDD; }
constexpr size_t kDnBase = kPuBase + (size_t)kNL * 4 * kDD; // 32M
__device__ __forceinline__ __host__ size_t dnOff(int i)  { return kDnBase + (size_t)i * 2 * kDD; }
constexpr size_t kLgBase = kDnBase + (size_t)kNL * 2 * kDD; // 40M
constexpr size_t kWTot = kLgBase + (size_t)kD * kV;         // 72.768M
__device__ __align__(1024) __half g_wh[kWTot];

// ---------------- small helpers ----------------
__device__ __forceinline__ uint32_t f2tf32(float f) {
    uint32_t u;
    asm("cvt.rna.tf32.f32 %0, %1;" : "=r"(u) : "f"(f));
    return u;
}
__device__ __forceinline__ void mma_tf32(float* c, const uint32_t* a, uint32_t b0, uint32_t b1) {
    asm volatile(
        "mma.sync.aligned.m16n8k8.row.col.f32.tf32.tf32.f32 "
        "{%0,%1,%2,%3}, {%4,%5,%6,%7}, {%8,%9}, {%0,%1,%2,%3};"
        : "+f"(c[0]), "+f"(c[1]), "+f"(c[2]), "+f"(c[3])
        : "r"(a[0]), "r"(a[1]), "r"(a[2]), "r"(a[3]), "r"(b0), "r"(b1));
}
__device__ __forceinline__ void mma_f16(float* c, const uint32_t* a, uint32_t b0, uint32_t b1) {
    asm volatile(
        "mma.sync.aligned.m16n8k16.row.col.f32.f16.f16.f32 "
        "{%0,%1,%2,%3}, {%4,%5,%6,%7}, {%8,%9}, {%0,%1,%2,%3};"
        : "+f"(c[0]), "+f"(c[1]), "+f"(c[2]), "+f"(c[3])
        : "r"(a[0]), "r"(a[1]), "r"(a[2]), "r"(a[3]), "r"(b0), "r"(b1));
}
__device__ __forceinline__ void cp16(uint32_t dst, const void* src) {
    asm volatile("cp.async.cg.shared.global [%0], [%1], 16;" :: "r"(dst), "l"(src));
}
__device__ __forceinline__ void ldsm4(uint32_t& r0, uint32_t& r1, uint32_t& r2, uint32_t& r3,
                                      uint32_t addr) {
    asm volatile("ldmatrix.sync.aligned.m8n8.x4.shared.b16 {%0,%1,%2,%3}, [%4];"
                 : "=r"(r0), "=r"(r1), "=r"(r2), "=r"(r3) : "r"(addr));
}

// ---------------- fp16 convert + transpose (batched over layers via grid.z) ----------
__global__ void cvt_t_kernel(const float* __restrict__ in, __half* __restrict__ out,
                             int K, int N, size_t srcStride, size_t dstStride)
{
    __shared__ __half tile[64][33];
    in  += (size_t)blockIdx.z * srcStride;
    out += (size_t)blockIdx.z * dstStride;
    int kb = blockIdx.y * 64, nb = blockIdx.x * 32;
    int tx = threadIdx.x & 31, ty = threadIdx.x >> 5;
#pragma unroll
    for (int r = ty; r < 64; r += 8)
        tile[r][tx] = __float2half_rn(in[(size_t)(kb + r) * N + nb + tx]);
    __syncthreads();
    int n  = threadIdx.x >> 3;
    int k0 = (threadIdx.x & 7) * 8;
    __half2 hv[4];
#pragma unroll
    for (int j = 0; j < 4; ++j)
        hv[j] = __halves2half2(tile[k0 + 2 * j][n], tile[k0 + 2 * j + 1][n]);
    *(uint4*)&out[(size_t)(nb + n) * K + kb + k0] = *(uint4*)hv;
}

// ---------------- fp32 -> fp16 convert (logits activations) ----------------
__global__ void cvt_h_kernel(const float* __restrict__ in,
                             __half* __restrict__ out, int n4)
{
    int i = blockIdx.x * blockDim.x + threadIdx.x;
    if (i >= n4) return;
    float4 v = ((const float4*)in)[i];
    __half2* op = (__half2*)(out + (size_t)i * 4);
    op[0] = __floats2half2_rn(v.x, v.y);
    op[1] = __floats2half2_rn(v.z, v.w);
}

// ---------------- bias concat kernels ----------------
__global__ void catbias3_kernel(const float* __restrict__ a, const float* __restrict__ b,
                                const float* __restrict__ c, float* __restrict__ o)
{
    int l = blockIdx.y;
    int i = blockIdx.x * 256 + threadIdx.x;
    float v;
    if (i < kD)           v = a[l * kD + i];
    else if (i < 2 * kD)  v = b[l * kD + i - kD];
    else                  v = c[l * kD + i - 2 * kD];
    o[(size_t)l * kQS + i] = v;
}
__global__ void catbias2_kernel(const float* __restrict__ a, const float* __restrict__ b,
                                float* __restrict__ o)
{
    int l = blockIdx.y;
    int i = blockIdx.x * 256 + threadIdx.x;
    float v = (i < kD2) ? a[l * kD2 + i] : b[l * kD2 + i - kD2];
    o[(size_t)l * kPU + i] = v;
}

// ---------------- embed + positional encoding ----------------
__global__ void embed_pe_kernel(const int* __restrict__ ids,
                                const float* __restrict__ embed,
                                float* __restrict__ x)
{
    int row = blockIdx.x;
    int l   = row % kL;
    int id  = ids[row];
    int d0  = threadIdx.x * 4;
    float4 ev = *(const float4*)&embed[(size_t)id * kD + d0];
    float out[4] = {ev.x, ev.y, ev.z, ev.w};
    const float negc = -0.0089944731f;   // -log(10000)/1024 in fp32
#pragma unroll
    for (int t = 0; t < 4; ++t) {
        int d  = d0 + t;
        int i2 = (d >> 1) * 2;
        float freq = expf((float)i2 * negc);
        float a    = (float)l * freq;
        out[t] += (d & 1) ? cosf(a) : sinf(a);
    }
    *(float4*)&x[(size_t)row * kD + d0] = make_float4(out[0], out[1], out[2], out[3]);
}

// ---------------- rmsnorm (emits fp16) ----------------
__global__ void rmsnorm_kernel(const float* __restrict__ x,
                               const float* __restrict__ gamma,
                               __half* __restrict__ y)
{
    int row = blockIdx.x;
    const float* xr = x + (size_t)row * kD;
    int d0 = threadIdx.x * 4;
    float4 v = *(const float4*)&xr[d0];
    float ss = v.x * v.x + v.y * v.y + v.z * v.z + v.w * v.w;
#pragma unroll
    for (int off = 16; off; off >>= 1)
        ss += __shfl_xor_sync(0xffffffffu, ss, off);
    __shared__ float ws[8];
    int lane = threadIdx.x & 31, w = threadIdx.x >> 5;
    if (lane == 0) ws[w] = ss;
    __syncthreads();
    if (w == 0) {
        float t = (lane < 8) ? ws[lane] : 0.0f;
#pragma unroll
        for (int off = 4; off; off >>= 1)
            t += __shfl_xor_sync(0xffffffffu, t, off);
        if (lane == 0) ws[0] = t;
    }
    __syncthreads();
    float scale = rsqrtf(ws[0] / (float)kD + EPSF);
    float4 g = *(const float4*)&gamma[d0];
    __half2* yp = (__half2*)&y[(size_t)row * kD + d0];
    yp[0] = __floats2half2_rn(v.x * scale * g.x, v.y * scale * g.y);
    yp[1] = __floats2half2_rn(v.z * scale * g.z, v.w * scale * g.w);
}

// ---------------- silu gate (fused fp16 proj|up input) ----------------
__global__ void silu_gate_kernel(const __half* __restrict__ pu,
                                 __half* __restrict__ gate)
{
    size_t t = ((size_t)blockIdx.x * blockDim.x + threadIdx.x) * 4;
    size_t row = t >> 11;
    int c = (int)(t & (kD2 - 1));
    const __half2* pp = (const __half2*)(pu + row * kPU + c);
    const __half2* uu = (const __half2*)(pu + row * kPU + kD2 + c);
    float2 p0 = __half22float2(pp[0]), p1 = __half22float2(pp[1]);
    float2 u0 = __half22float2(uu[0]), u1 = __half22float2(uu[1]);
    float t0 = p0.x * u0.x, t1 = p0.y * u0.y, t2 = p1.x * u1.x, t3 = p1.y * u1.y;
    float s0 = t0 / (1.0f + __expf(-t0));
    float s1 = t1 / (1.0f + __expf(-t1));
    float s2 = t2 / (1.0f + __expf(-t2));
    float s3 = t3 / (1.0f + __expf(-t3));
    __half2* gp = (__half2*)&gate[row * kD2 + c];
    gp[0] = __floats2half2_rn(s0, s1);
    gp[1] = __floats2half2_rn(s2, s3);
}

// ================= FP16 GEMM: 128x256 CTA tile, 8 warps of 64x64 =================
// C[M,N] = A[M,K] @ Bt[N,K]^T + bias (+resid). Warp grid 2(m) x 4(n).
// Smem pitch 80B per 32-half row. 3-stage cp.async ring. Requires N%256==0.

constexpr int kATile = 128 * 80;           // 10240 B (A: 128 rows)
constexpr int kBTile = 256 * 80;           // 20480 B (B: 256 rows)
constexpr int kStage = kATile + kBTile;    // 30720 B
constexpr int kGemmSmem = 3 * kStage;      // 92160 B

template<bool HOUT>
__global__ void __launch_bounds__(256, 1)
gemm_f16_kernel(const __half* __restrict__ A, const __half* __restrict__ Bt,
                const float* __restrict__ bias, const float* __restrict__ resid,
                void* __restrict__ Cv, int M, int N, int K)
{
    extern __shared__ char smem[];
    uint32_t base = (uint32_t)__cvta_generic_to_shared(smem);

    int tid  = threadIdx.x;
    int lane = tid & 31;
    int warp = tid >> 5;
    int wm = warp >> 2;                    // 0..1 (64 rows each)
    int wn = warp & 3;                     // 0..3 (64 cols each)
    int bm = blockIdx.y, bn = blockIdx.x;

    const __half* Ab = A  + (size_t)bm * 128 * K;
    const __half* Bb = Bt + (size_t)(bn * 256) * K;

    // cp.async decomposition: A 512 16B-chunks (2/thread), B 1024 (4/thread)
    int arw[2], asb[2], brw[4], bsb[4];
    uint32_t dstA[2], dstB[4];
#pragma unroll
    for (int i = 0; i < 2; ++i) {
        int c = i * 256 + tid;
        arw[i] = c >> 2; asb[i] = c & 3;
        dstA[i] = base + (uint32_t)(arw[i] * 80 + asb[i] * 16);
    }
#pragma unroll
    for (int i = 0; i < 4; ++i) {
        int c = i * 256 + tid;
        brw[i] = c >> 2; bsb[i] = c & 3;
        dstB[i] = base + (uint32_t)(kATile + brw[i] * 80 + bsb[i] * 16);
    }

    // ldmatrix addresses
    int q  = lane >> 3;
    int r8 = lane & 7;
    uint32_t aAddr = base + (uint32_t)((wm * 64 + (q & 1) * 8 + r8) * 80 + (q >> 1) * 16);
    uint32_t bAddr = base + (uint32_t)(kATile + (wn * 64 + (q & 1) * 8 + r8) * 80 + (q >> 1) * 16);

    float acc[4][8][4];
#pragma unroll
    for (int mt = 0; mt < 4; ++mt)
#pragma unroll
        for (int nt = 0; nt < 8; ++nt)
#pragma unroll
            for (int r = 0; r < 4; ++r) acc[mt][nt][r] = 0.0f;

    int nit = K >> 5;

    auto stage = [&](int k0, int b) {
        uint32_t boff = (uint32_t)(b * kStage);
#pragma unroll
        for (int i = 0; i < 2; ++i)
            cp16(dstA[i] + boff, &Ab[(size_t)arw[i] * K + k0 + asb[i] * 8]);
#pragma unroll
        for (int i = 0; i < 4; ++i)
            cp16(dstB[i] + boff, &Bb[(size_t)brw[i] * K + k0 + bsb[i] * 8]);
        asm volatile("cp.async.commit_group;");
    };

    stage(0, 0);
    if (nit > 1) stage(32, 1);

    int buf = 0;
    for (int it = 0; it < nit; ++it) {
        if (it + 1 < nit) asm volatile("cp.async.wait_group 1;");
        else              asm volatile("cp.async.wait_group 0;");
        __syncthreads();
        if (it + 2 < nit) {
            int nb = buf + 2; if (nb >= 3) nb -= 3;
            stage((it + 2) << 5, nb);
        }
        uint32_t bufoff = (uint32_t)(buf * kStage);
#pragma unroll
        for (int ks = 0; ks < 2; ++ks) {
            uint32_t koff = bufoff + (uint32_t)(ks * 32);
            uint32_t afr[4][4], bfr[8][2];
#pragma unroll
            for (int mt = 0; mt < 4; ++mt)
                ldsm4(afr[mt][0], afr[mt][1], afr[mt][2], afr[mt][3],
                      aAddr + koff + (uint32_t)(mt * 16 * 80));
#pragma unroll
            for (int np = 0; np < 4; ++np) {
                uint32_t r0, r1, r2, r3;
                ldsm4(r0, r1, r2, r3, bAddr + koff + (uint32_t)(np * 16 * 80));
                bfr[2 * np][0] = r0; bfr[2 * np + 1][0] = r1;
                bfr[2 * np][1] = r2; bfr[2 * np + 1][1] = r3;
            }
#pragma unroll
            for (int mt = 0; mt < 4; ++mt)
#pragma unroll
                for (int nt = 0; nt < 8; ++nt)
                    mma_f16(acc[mt][nt], afr[mt], bfr[nt][0], bfr[nt][1]);
        }
        if (++buf == 3) buf = 0;
    }

    int rb = bm * 128 + wm * 64 + (lane >> 2);
    int cb = bn * 256 + wn * 64 + (lane & 3) * 2;
#pragma unroll
    for (int mt = 0; mt < 4; ++mt) {
#pragma unroll
        for (int nt = 0; nt < 8; ++nt) {
            int r0 = rb + mt * 16;
            int c0 = cb + nt * 8;
            float b0 = bias[c0], b1 = bias[c0 + 1];
            size_t off0 = (size_t)r0 * N + c0;
            size_t off1 = (size_t)(r0 + 8) * N + c0;
            float v0 = acc[mt][nt][0] + b0, v1 = acc[mt][nt][1] + b1;
            float v2 = acc[mt][nt][2] + b0, v3 = acc[mt][nt][3] + b1;
            if (!HOUT) {
                float* C = (float*)Cv;
                if (resid) {
                    float2 rr0 = *(const float2*)&resid[off0];
                    float2 rr1 = *(const float2*)&resid[off1];
                    v0 += rr0.x; v1 += rr0.y; v2 += rr1.x; v3 += rr1.y;
                }
                *(float2*)&C[off0] = make_float2(v0, v1);
                *(float2*)&C[off1] = make_float2(v2, v3);
            } else {
                __half* C = (__half*)Cv;
                *(__half2*)&C[off0] = __floats2half2_rn(v0, v1);
                *(__half2*)&C[off1] = __floats2half2_rn(v2, v3);
            }
        }
    }
}

// ================= flash attention, TF32 MMA, fp16 fused-QKV input =================
constexpr int kKV = 68;
constexpr int kAttnSmem = (64 * kKV * 2 + 4 * 16 * kKV) * 4;  // 52224 bytes

__global__ void __launch_bounds__(128)
flash_attn_mma(const __half* __restrict__ QKV, __half* __restrict__ O)
{
    extern __shared__ uint32_t asmem[];
    uint32_t* Ks = asmem;
    uint32_t* Vs = asmem + 64 * kKV;
    float*    Ps = (float*)(asmem + 2 * 64 * kKV) + (threadIdx.x >> 5) * 16 * kKV;

    int tid = threadIdx.x, lane = tid & 31, w = tid >> 5;
    int g = lane >> 2, tg = lane & 3;
    int bh = blockIdx.y;
    int b  = bh >> 4;
    int h  = bh & 15;
    int q0 = blockIdx.x * 64;
    size_t baseq = ((size_t)b * kL) * kQS + (size_t)h * kDH;
    size_t obase = ((size_t)b * kL) * kD  + (size_t)h * kDH;
    int rlo = q0 + w * 16 + g;

    uint32_t qf[8][4];
    {
        const __half* Qp = QKV + baseq + (size_t)rlo * kQS;
#pragma unroll
        for (int ks = 0; ks < 8; ++ks) {
            int kk = ks * 8 + tg;
            qf[ks][0] = f2tf32(__half2float(Qp[kk]));
            qf[ks][1] = f2tf32(__half2float(Qp[(size_t)8 * kQS + kk]));
            qf[ks][2] = f2tf32(__half2float(Qp[kk + 4]));
            qf[ks][3] = f2tf32(__half2float(Qp[(size_t)8 * kQS + kk + 4]));
        }
    }

    float of[8][4];
#pragma unroll
    for (int nt = 0; nt < 8; ++nt)
#pragma unroll
        for (int e = 0; e < 4; ++e) of[nt][e] = 0.0f;
    float mlo = -1e30f, mhi = -1e30f, llo = 0.0f, lhi = 0.0f;

    int nkt = blockIdx.x + 1;
    for (int kt = 0; kt < nkt; ++kt) {
        int k0 = kt * 64;
        __syncthreads();
#pragma unroll
        for (int i = 0; i < 4; ++i) {
            int c = i * 128 + tid;
            int row = c >> 3;
            int h8  = (c & 7) * 8;
            size_t roff = baseq + (size_t)(k0 + row) * kQS + h8;
            uint4 kraw = *(const uint4*)&QKV[roff + kD];
            uint4 vraw = *(const uint4*)&QKV[roff + 2 * kD];
            const __half2* kh = (const __half2*)&kraw;
            const __half2* vh = (const __half2*)&vraw;
            uint32_t* kd = &Ks[row * kKV + h8];
            uint32_t* vd = &Vs[row * kKV + h8];
#pragma unroll
            for (int j = 0; j < 4; ++j) {
                float2 kf = __half22float2(kh[j]);
                float2 vf = __half22float2(vh[j]);
                kd[2 * j]     = f2tf32(kf.x);
                kd[2 * j + 1] = f2tf32(kf.y);
                vd[2 * j]     = f2tf32(vf.x);
                vd[2 * j + 1] = f2tf32(vf.y);
            }
        }
        __syncthreads();

        float s[8][4];
#pragma unroll
        for (int nt = 0; nt < 8; ++nt)
#pragma unroll
            for (int e = 0; e < 4; ++e) s[nt][e] = 0.0f;
#pragma unroll
        for (int ks = 0; ks < 8; ++ks) {
            int kk = ks * 8 + tg;
#pragma unroll
            for (int nt = 0; nt < 8; ++nt) {
                int n0 = nt * 8 + g;
                mma_tf32(s[nt], qf[ks], Ks[n0 * kKV + kk], Ks[n0 * kKV + kk + 4]);
            }
        }

        bool diag = (kt == blockIdx.x);
        float rmlo = -1e30f, rmhi = -1e30f;
#pragma unroll
        for (int nt = 0; nt < 8; ++nt) {
#pragma unroll
            for (int e = 0; e < 4; ++e) {
                float v = s[nt][e] * 0.125f;
                if (diag) {
                    int key = k0 + nt * 8 + 2 * tg + (e & 1);
                    int row = (e < 2) ? rlo : rlo + 8;
                    if (key > row) v = -1e30f;
                }
                s[nt][e] = v;
                if (e < 2) rmlo = fmaxf(rmlo, v); else rmhi = fmaxf(rmhi, v);
            }
        }
        rmlo = fmaxf(rmlo, __shfl_xor_sync(0xffffffffu, rmlo, 1));
        rmlo = fmaxf(rmlo, __shfl_xor_sync(0xffffffffu, rmlo, 2));
        rmhi = fmaxf(rmhi, __shfl_xor_sync(0xffffffffu, rmhi, 1));
        rmhi = fmaxf(rmhi, __shfl_xor_sync(0xffffffffu, rmhi, 2));
        float mnlo = fmaxf(mlo, rmlo), mnhi = fmaxf(mhi, rmhi);
        float clo = __expf(mlo - mnlo), chi = __expf(mhi - mnhi);
        mlo = mnlo; mhi = mnhi;

        float rslo = 0.0f, rshi = 0.0f;
#pragma unroll
        for (int nt = 0; nt < 8; ++nt) {
            float p0 = __expf(s[nt][0] - mlo);
            float p1 = __expf(s[nt][1] - mlo);
            float p2 = __expf(s[nt][2] - mhi);
            float p3 = __expf(s[nt][3] - mhi);
            rslo += p0 + p1; rshi += p2 + p3;
            int col = nt * 8 + 2 * tg;
            *(float2*)&Ps[g * kKV + col]       = make_float2(p0, p1);
            *(float2*)&Ps[(g + 8) * kKV + col] = make_float2(p2, p3);
        }
        rslo += __shfl_xor_sync(0xffffffffu, rslo, 1);
        rslo += __shfl_xor_sync(0xffffffffu, rslo, 2);
        rshi += __shfl_xor_sync(0xffffffffu, rshi, 1);
        rshi += __shfl_xor_sync(0xffffffffu, rshi, 2);
        llo = llo * clo + rslo;
        lhi = lhi * chi + rshi;
#pragma unroll
        for (int nt = 0; nt < 8; ++nt) {
            of[nt][0] *= clo; of[nt][1] *= clo;
            of[nt][2] *= chi; of[nt][3] *= chi;
        }
        __syncwarp();

#pragma unroll
        for (int ks = 0; ks < 8; ++ks) {
            int kk = ks * 8 + tg;
            uint32_t pa[4];
            pa[0] = f2tf32(Ps[g * kKV + kk]);
            pa[1] = f2tf32(Ps[(g + 8) * kKV + kk]);
            pa[2] = f2tf32(Ps[g * kKV + kk + 4]);
            pa[3] = f2tf32(Ps[(g + 8) * kKV + kk + 4]);
#pragma unroll
            for (int nt = 0; nt < 8; ++nt) {
                int n0 = nt * 8 + g;
                mma_tf32(of[nt], pa, Vs[kk * kKV + n0], Vs[(kk + 4) * kKV + n0]);
            }
        }
    }

    float ilo = 1.0f / llo, ihi = 1.0f / lhi;
#pragma unroll
    for (int nt = 0; nt < 8; ++nt) {
        int col = nt * 8 + 2 * tg;
        size_t off0 = obase + (size_t)rlo * kD + col;
        size_t off1 = obase + (size_t)(rlo + 8) * kD + col;
        *(__half2*)&O[off0] = __floats2half2_rn(of[nt][0] * ilo, of[nt][1] * ilo);
        *(__half2*)&O[off1] = __floats2half2_rn(of[nt][2] * ihi, of[nt][3] * ihi);
    }
}

// ---------------- host launcher ----------------
static void launch_gemm_f(const __half* A, const __half* Bt, const float* bias,
                          const float* resid, float* C, int M, int N, int K)
{
    dim3 grid(N / 256, M / 128);
    gemm_f16_kernel<false><<<grid, 256, kGemmSmem>>>(A, Bt, bias, resid, C, M, N, K);
}
static void launch_gemm_h(const __half* A, const __half* Bt, const float* bias,
                          __half* C, int M, int N, int K)
{
    dim3 grid(N / 256, M / 128);
    gemm_f16_kernel<true><<<grid, 256, kGemmSmem>>>(A, Bt, bias, nullptr, C, M, N, K);
}
static void launch_cvt_batch(const float* in, __half* out, int K, int N, int layers,
                             size_t sStride, size_t dStride)
{
    dim3 grid(N / 32, K / 64, layers);
    cvt_t_kernel<<<grid, 256>>>(in, out, K, N, sStride, dStride);
}

extern "C" void kernel_launch(void* const* d_in, const int* in_sizes, int n_in,
                              void* d_out, int out_size)
{
    const int*   ids    = (const int*)  d_in[0];
    const float* embed  = (const float*)d_in[1];
    const float* Wq     = (const float*)d_in[2];
    const float* bq     = (const float*)d_in[3];
    const float* Wk     = (const float*)d_in[4];
    const float* bk     = (const float*)d_in[5];
    const float* Wv     = (const float*)d_in[6];
    const float* bv     = (const float*)d_in[7];
    const float* Wo     = (const float*)d_in[8];
    const float* bo     = (const float*)d_in[9];
    const float* Wproj  = (const float*)d_in[10];
    const float* bproj  = (const float*)d_in[11];
    const float* Wup    = (const float*)d_in[12];
    const float* bup    = (const float*)d_in[13];
    const float* Wdown  = (const float*)d_in[14];
    const float* bdown  = (const float*)d_in[15];
    const float* gammas = (const float*)d_in[16];
    const float* Wlog   = (const float*)d_in[17];
    const float* blog   = (const float*)d_in[18];
    float* out = (float*)d_out;

    float *x, *bqkv, *bpu;
    __half *qkv, *pu, *h, *att, *gate, *wh;
    cudaGetSymbolAddress((void**)&x,    g_x);
    cudaGetSymbolAddress((void**)&qkv,  g_qkv);
    cudaGetSymbolAddress((void**)&pu,   g_pu);
    cudaGetSymbolAddress((void**)&bqkv, g_bqkv);
    cudaGetSymbolAddress((void**)&bpu,  g_bpu);
    cudaGetSymbolAddress((void**)&h,    g_h);
    cudaGetSymbolAddress((void**)&att,  g_att);
    cudaGetSymbolAddress((void**)&gate, g_gate);
    cudaGetSymbolAddress((void**)&wh,   g_wh);

    cudaFuncSetAttribute(gemm_f16_kernel<false>,
                         cudaFuncAttributeMaxDynamicSharedMemorySize, kGemmSmem);
    cudaFuncSetAttribute(gemm_f16_kernel<true>,
                         cudaFuncAttributeMaxDynamicSharedMemorySize, kGemmSmem);
    cudaFuncSetAttribute(flash_attn_mma,
                         cudaFuncAttributeMaxDynamicSharedMemorySize, kAttnSmem);

    // weight convert + transpose, batched per kind across layers (8 launches)
    launch_cvt_batch(Wq,    wh + qkvOff(0),           kD,  kD,  kNL, kDD,     3 * kDD);
    launch_cvt_batch(Wk,    wh + qkvOff(0) + kDD,     kD,  kD,  kNL, kDD,     3 * kDD);
    launch_cvt_batch(Wv,    wh + qkvOff(0) + 2 * kDD, kD,  kD,  kNL, kDD,     3 * kDD);
    launch_cvt_batch(Wo,    wh + kWoBase,             kD,  kD,  kNL, kDD,     kDD);
    launch_cvt_batch(Wproj, wh + kPuBase,             kD,  kD2, kNL, 2 * kDD, 4 * kDD);
    launch_cvt_batch(Wup,   wh + kPuBase + 2 * kDD,   kD,  kD2, kNL, 2 * kDD, 4 * kDD);
    launch_cvt_batch(Wdown, wh + kDnBase,             kD2, kD,  kNL, 2 * kDD, 2 * kDD);
    launch_cvt_batch(Wlog,  wh + kLgBase,             kD,  kV,  1,   0,       0);

    catbias3_kernel<<<dim3(kQS / 256, kNL), 256>>>(bq, bk, bv, bqkv);
    catbias2_kernel<<<dim3(kPU / 256, kNL), 256>>>(bproj, bup, bpu);

    embed_pe_kernel<<<kBL, 256>>>(ids, embed, x);

    for (int i = 0; i < kNL; ++i) {
        rmsnorm_kernel<<<kBL, 256>>>(x, gammas + (size_t)(2 * i) * kD, h);
        launch_gemm_h(h, wh + qkvOff(i), bqkv + (size_t)i * kQS, qkv, kBL, kQS, kD);
        flash_attn_mma<<<dim3(kL / 64, kB * kH), 128, kAttnSmem>>>(qkv, att);
        launch_gemm_f(att, wh + woOff(i), bo + (size_t)i * kD, x, x, kBL, kD, kD);
        rmsnorm_kernel<<<kBL, 256>>>(x, gammas + (size_t)(2 * i + 1) * kD, h);
        launch_gemm_h(h, wh + puOff(i), bpu + (size_t)i * kPU, pu, kBL, kPU, kD);
        silu_gate_kernel<<<((size_t)kBL * kD2) / (256 * 4), 256>>>(pu, gate);
        launch_gemm_f(gate, wh + dnOff(i), bdown + (size_t)i * kD, x, x, kBL, kD, kD2);
    }
    int n4 = (kBL * kD) / 4;
    cvt_h_kernel<<<(n4 + 255) / 256, 256>>>(x, h, n4);
    launch_gemm_f(h, wh + kLgBase, blog, nullptr, out, kBL, kV, kD);
}

// round 13
// speedup vs baseline: 1.2249x; 1.2249x over previous
#include <cuda_runtime.h>
#include <cuda_fp16.h>
#include <math.h>
#include <stdint.h>

// ---------------- problem constants ----------------
constexpr int kNL = 4;
constexpr int kD  = 1024;
constexpr int kD2 = 2048;
constexpr int kH  = 16;
constexpr int kDH = 64;
constexpr int kV  = 32000;
constexpr int kB  = 2;
constexpr int kL  = 2048;
constexpr int kBL = kB * kL;   // 4096
constexpr int kQS = 3 * kD;    // fused qkv row stride (3072)
constexpr int kPU = 2 * kD2;   // fused proj/up row stride (4096)
#define EPSF 1e-6f

// ---------------- scratch (device globals; no allocation allowed) ----------------
__device__ __align__(1024) float  g_x[kBL * kD];                  // residual (fp32)
__device__ __align__(1024) __half g_qkv[(size_t)kBL * kQS];       // fused q|k|v (fp16)
__device__ __align__(1024) __half g_pu[(size_t)kBL * kPU];        // fused proj|up (fp16)
__device__ __align__(1024) __half g_h[kBL * kD];                  // rmsnorm out / logits A
__device__ __align__(1024) __half g_att[kBL * kD];                // attention out
__device__ __align__(1024) __half g_gate[(size_t)kBL * kD2];      // silu out
__device__ __align__(1024) float  g_bqkv[kNL * kQS];              // fused qkv bias
__device__ __align__(1024) float  g_bpu[kNL * kPU];               // fused proj/up bias

// fp16 + TRANSPOSED weights, [N][K] blocks. Per-layer fused layouts.
constexpr size_t kDD = (size_t)kD * kD;                 // 1M
__device__ __forceinline__ __host__ size_t qkvOff(int i) { return (size_t)i * 3 * kDD; }
constexpr size_t kWoBase = (size_t)kNL * 3 * kDD;       // 12M
__device__ __forceinline__ __host__ size_t woOff(int i)  { return kWoBase + (size_t)i * kDD; }
constexpr size_t kPuBase = kWoBase + (size_t)kNL * kDD; // 16M
__device__ __forceinline__ __host__ size_t puOff(int i)  { return kPuBase + (size_t)i * 4 * kDD; }
constexpr size_t kDnBase = kPuBase + (size_t)kNL * 4 * kDD; // 32M
__device__ __forceinline__ __host__ size_t dnOff(int i)  { return kDnBase + (size_t)i * 2 * kDD; }
constexpr size_t kLgBase = kDnBase + (size_t)kNL * 2 * kDD; // 40M
constexpr size_t kWTot = kLgBase + (size_t)kD * kV;         // 72.768M
__device__ __align__(1024) __half g_wh[kWTot];

// ---------------- small helpers ----------------
__device__ __forceinline__ void mma_f16(float* c, const uint32_t* a, uint32_t b0, uint32_t b1) {
    asm volatile(
        "mma.sync.aligned.m16n8k16.row.col.f32.f16.f16.f32 "
        "{%0,%1,%2,%3}, {%4,%5,%6,%7}, {%8,%9}, {%0,%1,%2,%3};"
        : "+f"(c[0]), "+f"(c[1]), "+f"(c[2]), "+f"(c[3])
        : "r"(a[0]), "r"(a[1]), "r"(a[2]), "r"(a[3]), "r"(b0), "r"(b1));
}
__device__ __forceinline__ void cp16(uint32_t dst, const void* src) {
    asm volatile("cp.async.cg.shared.global [%0], [%1], 16;" :: "r"(dst), "l"(src));
}
__device__ __forceinline__ void ldsm4(uint32_t& r0, uint32_t& r1, uint32_t& r2, uint32_t& r3,
                                      uint32_t addr) {
    asm volatile("ldmatrix.sync.aligned.m8n8.x4.shared.b16 {%0,%1,%2,%3}, [%4];"
                 : "=r"(r0), "=r"(r1), "=r"(r2), "=r"(r3) : "r"(addr));
}
__device__ __forceinline__ void ldsm4t(uint32_t& r0, uint32_t& r1, uint32_t& r2, uint32_t& r3,
                                       uint32_t addr) {
    asm volatile("ldmatrix.sync.aligned.m8n8.x4.trans.shared.b16 {%0,%1,%2,%3}, [%4];"
                 : "=r"(r0), "=r"(r1), "=r"(r2), "=r"(r3) : "r"(addr));
}

// ---------------- fp16 convert + transpose (batched over layers via grid.z) ----------
__global__ void cvt_t_kernel(const float* __restrict__ in, __half* __restrict__ out,
                             int K, int N, size_t srcStride, size_t dstStride)
{
    __shared__ __half tile[64][33];
    in  += (size_t)blockIdx.z * srcStride;
    out += (size_t)blockIdx.z * dstStride;
    int kb = blockIdx.y * 64, nb = blockIdx.x * 32;
    int tx = threadIdx.x & 31, ty = threadIdx.x >> 5;
#pragma unroll
    for (int r = ty; r < 64; r += 8)
        tile[r][tx] = __float2half_rn(in[(size_t)(kb + r) * N + nb + tx]);
    __syncthreads();
    int n  = threadIdx.x >> 3;
    int k0 = (threadIdx.x & 7) * 8;
    __half2 hv[4];
#pragma unroll
    for (int j = 0; j < 4; ++j)
        hv[j] = __halves2half2(tile[k0 + 2 * j][n], tile[k0 + 2 * j + 1][n]);
    *(uint4*)&out[(size_t)(nb + n) * K + kb + k0] = *(uint4*)hv;
}

// ---------------- fp32 -> fp16 convert (logits activations) ----------------
__global__ void cvt_h_kernel(const float* __restrict__ in,
                             __half* __restrict__ out, int n4)
{
    int i = blockIdx.x * blockDim.x + threadIdx.x;
    if (i >= n4) return;
    float4 v = ((const float4*)in)[i];
    __half2* op = (__half2*)(out + (size_t)i * 4);
    op[0] = __floats2half2_rn(v.x, v.y);
    op[1] = __floats2half2_rn(v.z, v.w);
}

// ---------------- bias concat kernels ----------------
__global__ void catbias3_kernel(const float* __restrict__ a, const float* __restrict__ b,
                                const float* __restrict__ c, float* __restrict__ o)
{
    int l = blockIdx.y;
    int i = blockIdx.x * 256 + threadIdx.x;
    float v;
    if (i < kD)           v = a[l * kD + i];
    else if (i < 2 * kD)  v = b[l * kD + i - kD];
    else                  v = c[l * kD + i - 2 * kD];
    o[(size_t)l * kQS + i] = v;
}
__global__ void catbias2_kernel(const float* __restrict__ a, const float* __restrict__ b,
                                float* __restrict__ o)
{
    int l = blockIdx.y;
    int i = blockIdx.x * 256 + threadIdx.x;
    float v = (i < kD2) ? a[l * kD2 + i] : b[l * kD2 + i - kD2];
    o[(size_t)l * kPU + i] = v;
}

// ---------------- embed + positional encoding ----------------
__global__ void embed_pe_kernel(const int* __restrict__ ids,
                                const float* __restrict__ embed,
                                float* __restrict__ x)
{
    int row = blockIdx.x;
    int l   = row % kL;
    int id  = ids[row];
    int d0  = threadIdx.x * 4;
    float4 ev = *(const float4*)&embed[(size_t)id * kD + d0];
    float out[4] = {ev.x, ev.y, ev.z, ev.w};
    const float negc = -0.0089944731f;   // -log(10000)/1024 in fp32
#pragma unroll
    for (int t = 0; t < 4; ++t) {
        int d  = d0 + t;
        int i2 = (d >> 1) * 2;
        float freq = expf((float)i2 * negc);
        float a    = (float)l * freq;
        out[t] += (d & 1) ? cosf(a) : sinf(a);
    }
    *(float4*)&x[(size_t)row * kD + d0] = make_float4(out[0], out[1], out[2], out[3]);
}

// ---------------- rmsnorm (emits fp16) ----------------
__global__ void rmsnorm_kernel(const float* __restrict__ x,
                               const float* __restrict__ gamma,
                               __half* __restrict__ y)
{
    int row = blockIdx.x;
    const float* xr = x + (size_t)row * kD;
    int d0 = threadIdx.x * 4;
    float4 v = *(const float4*)&xr[d0];
    float ss = v.x * v.x + v.y * v.y + v.z * v.z + v.w * v.w;
#pragma unroll
    for (int off = 16; off; off >>= 1)
        ss += __shfl_xor_sync(0xffffffffu, ss, off);
    __shared__ float ws[8];
    int lane = threadIdx.x & 31, w = threadIdx.x >> 5;
    if (lane == 0) ws[w] = ss;
    __syncthreads();
    if (w == 0) {
        float t = (lane < 8) ? ws[lane] : 0.0f;
#pragma unroll
        for (int off = 4; off; off >>= 1)
            t += __shfl_xor_sync(0xffffffffu, t, off);
        if (lane == 0) ws[0] = t;
    }
    __syncthreads();
    float scale = rsqrtf(ws[0] / (float)kD + EPSF);
    float4 g = *(const float4*)&gamma[d0];
    __half2* yp = (__half2*)&y[(size_t)row * kD + d0];
    yp[0] = __floats2half2_rn(v.x * scale * g.x, v.y * scale * g.y);
    yp[1] = __floats2half2_rn(v.z * scale * g.z, v.w * scale * g.w);
}

// ---------------- silu gate (fused fp16 proj|up input) ----------------
__global__ void silu_gate_kernel(const __half* __restrict__ pu,
                                 __half* __restrict__ gate)
{
    size_t t = ((size_t)blockIdx.x * blockDim.x + threadIdx.x) * 4;
    size_t row = t >> 11;
    int c = (int)(t & (kD2 - 1));
    const __half2* pp = (const __half2*)(pu + row * kPU + c);
    const __half2* uu = (const __half2*)(pu + row * kPU + kD2 + c);
    float2 p0 = __half22float2(pp[0]), p1 = __half22float2(pp[1]);
    float2 u0 = __half22float2(uu[0]), u1 = __half22float2(uu[1]);
    float t0 = p0.x * u0.x, t1 = p0.y * u0.y, t2 = p1.x * u1.x, t3 = p1.y * u1.y;
    float s0 = t0 / (1.0f + __expf(-t0));
    float s1 = t1 / (1.0f + __expf(-t1));
    float s2 = t2 / (1.0f + __expf(-t2));
    float s3 = t3 / (1.0f + __expf(-t3));
    __half2* gp = (__half2*)&gate[row * kD2 + c];
    gp[0] = __floats2half2_rn(s0, s1);
    gp[1] = __floats2half2_rn(s2, s3);
}

// ================= FP16 tensor-core GEMM (R11 proven 128x128, 3-stage) =================
constexpr int kABytes = 128 * 40 * 2;      // 10240 bytes per operand tile
constexpr int kBufBytes = 2 * kABytes;     // 20480 per stage (A+B)
constexpr int kGemmSmem = 3 * kBufBytes;   // 61440

template<bool HOUT>
__global__ void __launch_bounds__(256, 2)
gemm_f16_kernel(const __half* __restrict__ A, const __half* __restrict__ Bt,
                const float* __restrict__ bias, const float* __restrict__ resid,
                void* __restrict__ Cv, int M, int N, int K)
{
    extern __shared__ char smem[];
    uint32_t base = (uint32_t)__cvta_generic_to_shared(smem);

    int tid  = threadIdx.x;
    int lane = tid & 31;
    int warp = tid >> 5;
    int wm = warp >> 2;
    int wn = warp & 3;
    int bm = blockIdx.y, bn = blockIdx.x;

    const __half* Ab = A  + (size_t)bm * 128 * K;
    const __half* Bb = Bt + (size_t)(bn * 128) * K;

    int rw[2], sub[2];
    uint32_t dstA[2], dstB[2];
#pragma unroll
    for (int i = 0; i < 2; ++i) {
        int c = i * 256 + tid;
        rw[i]  = c >> 2;
        sub[i] = c & 3;
        dstA[i] = base + (uint32_t)(rw[i] * 80 + sub[i] * 16);
        dstB[i] = base + (uint32_t)(kABytes + rw[i] * 80 + sub[i] * 16);
    }

    int q  = lane >> 3;
    int r8 = lane & 7;
    uint32_t aAddr = base + (uint32_t)((wm * 64 + (q & 1) * 8 + r8) * 80 + (q >> 1) * 16);
    uint32_t bAddr = base + (uint32_t)(kABytes + (wn * 32 + (q & 1) * 8 + r8) * 80 + (q >> 1) * 16);

    float acc[4][4][4];
#pragma unroll
    for (int mt = 0; mt < 4; ++mt)
#pragma unroll
        for (int nt = 0; nt < 4; ++nt)
#pragma unroll
            for (int r = 0; r < 4; ++r) acc[mt][nt][r] = 0.0f;

    int nit = K >> 5;

    auto stage = [&](int k0, int b) {
        uint32_t boff = (uint32_t)(b * kBufBytes);
#pragma unroll
        for (int i = 0; i < 2; ++i) {
            cp16(dstA[i] + boff, &Ab[(size_t)rw[i] * K + k0 + sub[i] * 8]);
            cp16(dstB[i] + boff, &Bb[(size_t)rw[i] * K + k0 + sub[i] * 8]);
        }
        asm volatile("cp.async.commit_group;");
    };

    stage(0, 0);
    if (nit > 1) stage(32, 1);

    int buf = 0;
    for (int it = 0; it < nit; ++it) {
        if (it + 1 < nit) asm volatile("cp.async.wait_group 1;");
        else              asm volatile("cp.async.wait_group 0;");
        __syncthreads();
        if (it + 2 < nit) {
            int nb = buf + 2; if (nb >= 3) nb -= 3;
            stage((it + 2) << 5, nb);
        }
        uint32_t bufoff = (uint32_t)(buf * kBufBytes);
#pragma unroll
        for (int ks = 0; ks < 2; ++ks) {
            uint32_t koff = bufoff + (uint32_t)(ks * 32);
            uint32_t afr[4][4], bfr[4][2];
#pragma unroll
            for (int mt = 0; mt < 4; ++mt)
                ldsm4(afr[mt][0], afr[mt][1], afr[mt][2], afr[mt][3],
                      aAddr + koff + (uint32_t)(mt * 16 * 80));
#pragma unroll
            for (int ntp = 0; ntp < 2; ++ntp) {
                uint32_t r0, r1, r2, r3;
                ldsm4(r0, r1, r2, r3, bAddr + koff + (uint32_t)(ntp * 16 * 80));
                bfr[2 * ntp][0] = r0; bfr[2 * ntp + 1][0] = r1;
                bfr[2 * ntp][1] = r2; bfr[2 * ntp + 1][1] = r3;
            }
#pragma unroll
            for (int mt = 0; mt < 4; ++mt)
#pragma unroll
                for (int nt = 0; nt < 4; ++nt)
                    mma_f16(acc[mt][nt], afr[mt], bfr[nt][0], bfr[nt][1]);
        }
        if (++buf == 3) buf = 0;
    }

    int rb = bm * 128 + wm * 64 + (lane >> 2);
    int cb = bn * 128 + wn * 32 + (lane & 3) * 2;
#pragma unroll
    for (int mt = 0; mt < 4; ++mt) {
#pragma unroll
        for (int nt = 0; nt < 4; ++nt) {
            int r0 = rb + mt * 16;
            int c0 = cb + nt * 8;
            float b0 = bias[c0], b1 = bias[c0 + 1];
            size_t off0 = (size_t)r0 * N + c0;
            size_t off1 = (size_t)(r0 + 8) * N + c0;
            float v0 = acc[mt][nt][0] + b0, v1 = acc[mt][nt][1] + b1;
            float v2 = acc[mt][nt][2] + b0, v3 = acc[mt][nt][3] + b1;
            if (!HOUT) {
                float* C = (float*)Cv;
                if (resid) {
                    float2 rr0 = *(const float2*)&resid[off0];
                    float2 rr1 = *(const float2*)&resid[off1];
                    v0 += rr0.x; v1 += rr0.y; v2 += rr1.x; v3 += rr1.y;
                }
                *(float2*)&C[off0] = make_float2(v0, v1);
                *(float2*)&C[off1] = make_float2(v2, v3);
            } else {
                __half* C = (__half*)Cv;
                *(__half2*)&C[off0] = __floats2half2_rn(v0, v1);
                *(__half2*)&C[off1] = __floats2half2_rn(v2, v3);
            }
        }
    }
}

// ================= flash attention, FP16 MMA end-to-end =================
// 128 threads / 4 warps, warp = 16 q-rows. Ks/Vs raw fp16 [64][72]; P fp16.
// QK: m16n8k16 with B via ldsm4 (normal) on Ks. PV: B via ldsm4.trans on Vs.
constexpr int kKVp = 72;   // smem pitch (halves)
constexpr int kAttnSmem = (2 * 64 * kKVp + 4 * 16 * kKVp) * 2;  // 27648 B

__global__ void __launch_bounds__(128)
flash_attn_f16(const __half* __restrict__ QKV, __half* __restrict__ O)
{
    extern __shared__ __half hsm[];
    __half* Ks = hsm;
    __half* Vs = hsm + 64 * kKVp;
    __half* Ps = hsm + 2 * 64 * kKVp + (threadIdx.x >> 5) * 16 * kKVp;
    uint32_t ksBase = (uint32_t)__cvta_generic_to_shared(Ks);
    uint32_t vsBase = (uint32_t)__cvta_generic_to_shared(Vs);

    int tid = threadIdx.x, lane = tid & 31, w = tid >> 5;
    int g = lane >> 2, tg = lane & 3;
    int q  = lane >> 3;       // ldsm quad
    int r8 = lane & 7;
    int bh = blockIdx.y;
    int b  = bh >> 4;
    int h  = bh & 15;
    int q0 = blockIdx.x * 64;
    size_t baseq = ((size_t)b * kL) * kQS + (size_t)h * kDH;
    size_t obase = ((size_t)b * kL) * kD  + (size_t)h * kDH;
    int rlo = q0 + w * 16 + g;

    // ldsm base addresses: quad q -> (row + (q&1)*8, col + (q>>1)*8)
    uint32_t kAddr = ksBase + (uint32_t)((((q & 1) * 8 + r8) * kKVp + (q >> 1) * 8) * 2);
    uint32_t vAddr = vsBase + (uint32_t)((((q & 1) * 8 + r8) * kKVp + (q >> 1) * 8) * 2);

    // Q fragments (fp16, resident): 4 k16-steps
    uint32_t qf[4][4];
    {
        const __half* Qp = QKV + baseq + (size_t)rlo * kQS;
#pragma unroll
        for (int ks = 0; ks < 4; ++ks) {
            int kk = ks * 16 + 2 * tg;
            qf[ks][0] = *(const uint32_t*)&Qp[kk];
            qf[ks][1] = *(const uint32_t*)&Qp[(size_t)8 * kQS + kk];
            qf[ks][2] = *(const uint32_t*)&Qp[kk + 8];
            qf[ks][3] = *(const uint32_t*)&Qp[(size_t)8 * kQS + kk + 8];
        }
    }

    float of[8][4];
#pragma unroll
    for (int nt = 0; nt < 8; ++nt)
#pragma unroll
        for (int e = 0; e < 4; ++e) of[nt][e] = 0.0f;
    float mlo = -1e30f, mhi = -1e30f, llo = 0.0f, lhi = 0.0f;

    int nkt = blockIdx.x + 1;
    for (int kt = 0; kt < nkt; ++kt) {
        int k0 = kt * 64;
        __syncthreads();
        // raw fp16 K/V tile copy (no conversion)
#pragma unroll
        for (int i = 0; i < 4; ++i) {
            int c = i * 128 + tid;
            int row = c >> 3;
            int h8  = (c & 7) * 8;
            size_t roff = baseq + (size_t)(k0 + row) * kQS + h8;
            *(uint4*)&Ks[row * kKVp + h8] = *(const uint4*)&QKV[roff + kD];
            *(uint4*)&Vs[row * kKVp + h8] = *(const uint4*)&QKV[roff + 2 * kD];
        }
        __syncthreads();

        // S = Q @ K^T  (fp16 MMA, 4 k16-steps)
        float s[8][4];
#pragma unroll
        for (int nt = 0; nt < 8; ++nt)
#pragma unroll
            for (int e = 0; e < 4; ++e) s[nt][e] = 0.0f;
#pragma unroll
        for (int ks = 0; ks < 4; ++ks) {
            uint32_t bfr[8][2];
#pragma unroll
            for (int np = 0; np < 4; ++np) {   // 4 n16 key tiles
                uint32_t r0, r1, r2, r3;
                ldsm4(r0, r1, r2, r3,
                      kAddr + (uint32_t)(((np * 16) * kKVp + ks * 16) * 2));
                bfr[2 * np][0] = r0; bfr[2 * np + 1][0] = r1;
                bfr[2 * np][1] = r2; bfr[2 * np + 1][1] = r3;
            }
#pragma unroll
            for (int nt = 0; nt < 8; ++nt)
                mma_f16(s[nt], qf[ks], bfr[nt][0], bfr[nt][1]);
        }

        bool diag = (kt == blockIdx.x);
        float rmlo = -1e30f, rmhi = -1e30f;
#pragma unroll
        for (int nt = 0; nt < 8; ++nt) {
#pragma unroll
            for (int e = 0; e < 4; ++e) {
                float v = s[nt][e] * 0.125f;
                if (diag) {
                    int key = k0 + nt * 8 + 2 * tg + (e & 1);
                    int row = (e < 2) ? rlo : rlo + 8;
                    if (key > row) v = -1e30f;
                }
                s[nt][e] = v;
                if (e < 2) rmlo = fmaxf(rmlo, v); else rmhi = fmaxf(rmhi, v);
            }
        }
        rmlo = fmaxf(rmlo, __shfl_xor_sync(0xffffffffu, rmlo, 1));
        rmlo = fmaxf(rmlo, __shfl_xor_sync(0xffffffffu, rmlo, 2));
        rmhi = fmaxf(rmhi, __shfl_xor_sync(0xffffffffu, rmhi, 1));
        rmhi = fmaxf(rmhi, __shfl_xor_sync(0xffffffffu, rmhi, 2));
        float mnlo = fmaxf(mlo, rmlo), mnhi = fmaxf(mhi, rmhi);
        float clo = __expf(mlo - mnlo), chi = __expf(mhi - mnhi);
        mlo = mnlo; mhi = mnhi;

        float rslo = 0.0f, rshi = 0.0f;
#pragma unroll
        for (int nt = 0; nt < 8; ++nt) {
            float p0 = __expf(s[nt][0] - mlo);
            float p1 = __expf(s[nt][1] - mlo);
            float p2 = __expf(s[nt][2] - mhi);
            float p3 = __expf(s[nt][3] - mhi);
            rslo += p0 + p1; rshi += p2 + p3;
            int col = nt * 8 + 2 * tg;
            *(__half2*)&Ps[g * kKVp + col]       = __floats2half2_rn(p0, p1);
            *(__half2*)&Ps[(g + 8) * kKVp + col] = __floats2half2_rn(p2, p3);
        }
        rslo += __shfl_xor_sync(0xffffffffu, rslo, 1);
        rslo += __shfl_xor_sync(0xffffffffu, rslo, 2);
        rshi += __shfl_xor_sync(0xffffffffu, rshi, 1);
        rshi += __shfl_xor_sync(0xffffffffu, rshi, 2);
        llo = llo * clo + rslo;
        lhi = lhi * chi + rshi;
#pragma unroll
        for (int nt = 0; nt < 8; ++nt) {
            of[nt][0] *= clo; of[nt][1] *= clo;
            of[nt][2] *= chi; of[nt][3] *= chi;
        }
        __syncwarp();

        // O += P @ V  (fp16 MMA; V B-fragments via ldsm.trans)
#pragma unroll
        for (int ks = 0; ks < 4; ++ks) {
            int kk = ks * 16;
            uint32_t pa[4];
            pa[0] = *(const uint32_t*)&Ps[g * kKVp + kk + 2 * tg];
            pa[1] = *(const uint32_t*)&Ps[(g + 8) * kKVp + kk + 2 * tg];
            pa[2] = *(const uint32_t*)&Ps[g * kKVp + kk + 8 + 2 * tg];
            pa[3] = *(const uint32_t*)&Ps[(g + 8) * kKVp + kk + 8 + 2 * tg];
            uint32_t bfr[8][2];
#pragma unroll
            for (int np = 0; np < 4; ++np) {   // 4 n16 dh tiles
                uint32_t r0, r1, r2, r3;
                ldsm4t(r0, r1, r2, r3,
                       vAddr + (uint32_t)((kk * kKVp + np * 16) * 2));
                bfr[2 * np][0] = r0; bfr[2 * np][1] = r1;
                bfr[2 * np + 1][0] = r2; bfr[2 * np + 1][1] = r3;
            }
#pragma unroll
            for (int nt = 0; nt < 8; ++nt)
                mma_f16(of[nt], pa, bfr[nt][0], bfr[nt][1]);
        }
        __syncwarp();   // Ps reads done before next tile overwrites
    }

    float ilo = 1.0f / llo, ihi = 1.0f / lhi;
#pragma unroll
    for (int nt = 0; nt < 8; ++nt) {
        int col = nt * 8 + 2 * tg;
        size_t off0 = obase + (size_t)rlo * kD + col;
        size_t off1 = obase + (size_t)(rlo + 8) * kD + col;
        *(__half2*)&O[off0] = __floats2half2_rn(of[nt][0] * ilo, of[nt][1] * ilo);
        *(__half2*)&O[off1] = __floats2half2_rn(of[nt][2] * ihi, of[nt][3] * ihi);
    }
}

// ---------------- host launcher ----------------
static void launch_gemm_f(const __half* A, const __half* Bt, const float* bias,
                          const float* resid, float* C, int M, int N, int K)
{
    dim3 grid(N / 128, M / 128);
    gemm_f16_kernel<false><<<grid, 256, kGemmSmem>>>(A, Bt, bias, resid, C, M, N, K);
}
static void launch_gemm_h(const __half* A, const __half* Bt, const float* bias,
                          __half* C, int M, int N, int K)
{
    dim3 grid(N / 128, M / 128);
    gemm_f16_kernel<true><<<grid, 256, kGemmSmem>>>(A, Bt, bias, nullptr, C, M, N, K);
}
static void launch_cvt_batch(const float* in, __half* out, int K, int N, int layers,
                             size_t sStride, size_t dStride)
{
    dim3 grid(N / 32, K / 64, layers);
    cvt_t_kernel<<<grid, 256>>>(in, out, K, N, sStride, dStride);
}

extern "C" void kernel_launch(void* const* d_in, const int* in_sizes, int n_in,
                              void* d_out, int out_size)
{
    const int*   ids    = (const int*)  d_in[0];
    const float* embed  = (const float*)d_in[1];
    const float* Wq     = (const float*)d_in[2];
    const float* bq     = (const float*)d_in[3];
    const float* Wk     = (const float*)d_in[4];
    const float* bk     = (const float*)d_in[5];
    const float* Wv     = (const float*)d_in[6];
    const float* bv     = (const float*)d_in[7];
    const float* Wo     = (const float*)d_in[8];
    const float* bo     = (const float*)d_in[9];
    const float* Wproj  = (const float*)d_in[10];
    const float* bproj  = (const float*)d_in[11];
    const float* Wup    = (const float*)d_in[12];
    const float* bup    = (const float*)d_in[13];
    const float* Wdown  = (const float*)d_in[14];
    const float* bdown  = (const float*)d_in[15];
    const float* gammas = (const float*)d_in[16];
    const float* Wlog   = (const float*)d_in[17];
    const float* blog   = (const float*)d_in[18];
    float* out = (float*)d_out;

    float *x, *bqkv, *bpu;
    __half *qkv, *pu, *h, *att, *gate, *wh;
    cudaGetSymbolAddress((void**)&x,    g_x);
    cudaGetSymbolAddress((void**)&qkv,  g_qkv);
    cudaGetSymbolAddress((void**)&pu,   g_pu);
    cudaGetSymbolAddress((void**)&bqkv, g_bqkv);
    cudaGetSymbolAddress((void**)&bpu,  g_bpu);
    cudaGetSymbolAddress((void**)&h,    g_h);
    cudaGetSymbolAddress((void**)&att,  g_att);
    cudaGetSymbolAddress((void**)&gate, g_gate);
    cudaGetSymbolAddress((void**)&wh,   g_wh);

    cudaFuncSetAttribute(gemm_f16_kernel<false>,
                         cudaFuncAttributeMaxDynamicSharedMemorySize, kGemmSmem);
    cudaFuncSetAttribute(gemm_f16_kernel<true>,
                         cudaFuncAttributeMaxDynamicSharedMemorySize, kGemmSmem);

    // weight convert + transpose, batched per kind across layers (8 launches)
    launch_cvt_batch(Wq,    wh + qkvOff(0),           kD,  kD,  kNL, kDD,     3 * kDD);
    launch_cvt_batch(Wk,    wh + qkvOff(0) + kDD,     kD,  kD,  kNL, kDD,     3 * kDD);
    launch_cvt_batch(Wv,    wh + qkvOff(0) + 2 * kDD, kD,  kD,  kNL, kDD,     3 * kDD);
    launch_cvt_batch(Wo,    wh + kWoBase,             kD,  kD,  kNL, kDD,     kDD);
    launch_cvt_batch(Wproj, wh + kPuBase,             kD,  kD2, kNL, 2 * kDD, 4 * kDD);
    launch_cvt_batch(Wup,   wh + kPuBase + 2 * kDD,   kD,  kD2, kNL, 2 * kDD, 4 * kDD);
    launch_cvt_batch(Wdown, wh + kDnBase,             kD2, kD,  kNL, 2 * kDD, 2 * kDD);
    launch_cvt_batch(Wlog,  wh + kLgBase,             kD,  kV,  1,   0,       0);

    catbias3_kernel<<<dim3(kQS / 256, kNL), 256>>>(bq, bk, bv, bqkv);
    catbias2_kernel<<<dim3(kPU / 256, kNL), 256>>>(bproj, bup, bpu);

    embed_pe_kernel<<<kBL, 256>>>(ids, embed, x);

    for (int i = 0; i < kNL; ++i) {
        rmsnorm_kernel<<<kBL, 256>>>(x, gammas + (size_t)(2 * i) * kD, h);
        launch_gemm_h(h, wh + qkvOff(i), bqkv + (size_t)i * kQS, qkv, kBL, kQS, kD);
        flash_attn_f16<<<dim3(kL / 64, kB * kH), 128, kAttnSmem>>>(qkv, att);
        launch_gemm_f(att, wh + woOff(i), bo + (size_t)i * kD, x, x, kBL, kD, kD);
        rmsnorm_kernel<<<kBL, 256>>>(x, gammas + (size_t)(2 * i + 1) * kD, h);
        launch_gemm_h(h, wh + puOff(i), bpu + (size_t)i * kPU, pu, kBL, kPU, kD);
        silu_gate_kernel<<<((size_t)kBL * kD2) / (256 * 4), 256>>>(pu, gate);
        launch_gemm_f(gate, wh + dnOff(i), bdown + (size_t)i * kD, x, x, kBL, kD, kD2);
    }
    int n4 = (kBL * kD) / 4;
    cvt_h_kernel<<<(n4 + 255) / 256, 256>>>(x, h, n4);
    launch_gemm_f(h, wh + kLgBase, blog, nullptr, out, kBL, kV, kD);
}

// round 14
// speedup vs baseline: 1.4252x; 1.1635x over previous
#include <cuda_runtime.h>
#include <cuda_fp16.h>
#include <math.h>
#include <stdint.h>

// ---------------- problem constants ----------------
constexpr int kNL = 4;
constexpr int kD  = 1024;
constexpr int kD2 = 2048;
constexpr int kH  = 16;
constexpr int kDH = 64;
constexpr int kV  = 32000;
constexpr int kB  = 2;
constexpr int kL  = 2048;
constexpr int kBL = kB * kL;   // 4096
constexpr int kQS = 3 * kD;    // fused qkv row stride (3072)
constexpr int kPU = 2 * kD2;   // fused proj/up row stride (4096)
#define EPSF 1e-6f

// ---------------- scratch (device globals; no allocation allowed) ----------------
__device__ __align__(1024) float  g_x[kBL * kD];                  // residual (fp32)
__device__ __align__(1024) __half g_qkv[(size_t)kBL * kQS];       // fused q|k|v (fp16)
__device__ __align__(1024) __half g_pu[(size_t)kBL * kPU];        // fused proj|up (fp16)
__device__ __align__(1024) __half g_h[kBL * kD];                  // rmsnorm out / logits A
__device__ __align__(1024) __half g_att[kBL * kD];                // attention out
__device__ __align__(1024) __half g_gate[(size_t)kBL * kD2];      // silu out
__device__ __align__(1024) float  g_bqkv[kNL * kQS];              // fused qkv bias
__device__ __align__(1024) float  g_bpu[kNL * kPU];               // fused proj/up bias

// fp16 weights in NATURAL [K][N] layout (fused along N). Per-layer blocks.
constexpr size_t kDD = (size_t)kD * kD;                 // 1M
__device__ __forceinline__ __host__ size_t qkvOff(int i) { return (size_t)i * 3 * kDD; }
constexpr size_t kWoBase = (size_t)kNL * 3 * kDD;       // 12M
__device__ __forceinline__ __host__ size_t woOff(int i)  { return kWoBase + (size_t)i * kDD; }
constexpr size_t kPuBase = kWoBase + (size_t)kNL * kDD; // 16M
__device__ __forceinline__ __host__ size_t puOff(int i)  { return kPuBase + (size_t)i * 4 * kDD; }
constexpr size_t kDnBase = kPuBase + (size_t)kNL * 4 * kDD; // 32M
__device__ __forceinline__ __host__ size_t dnOff(int i)  { return kDnBase + (size_t)i * 2 * kDD; }
constexpr size_t kLgBase = kDnBase + (size_t)kNL * 2 * kDD; // 40M
constexpr size_t kWTot = kLgBase + (size_t)kD * kV;         // 72.768M
__device__ __align__(1024) __half g_wh[kWTot];

// ---------------- small helpers ----------------
__device__ __forceinline__ void mma_f16(float* c, const uint32_t* a, uint32_t b0, uint32_t b1) {
    asm volatile(
        "mma.sync.aligned.m16n8k16.row.col.f32.f16.f16.f32 "
        "{%0,%1,%2,%3}, {%4,%5,%6,%7}, {%8,%9}, {%0,%1,%2,%3};"
        : "+f"(c[0]), "+f"(c[1]), "+f"(c[2]), "+f"(c[3])
        : "r"(a[0]), "r"(a[1]), "r"(a[2]), "r"(a[3]), "r"(b0), "r"(b1));
}
__device__ __forceinline__ void cp16(uint32_t dst, const void* src) {
    asm volatile("cp.async.cg.shared.global [%0], [%1], 16;" :: "r"(dst), "l"(src));
}
__device__ __forceinline__ void ldsm4(uint32_t& r0, uint32_t& r1, uint32_t& r2, uint32_t& r3,
                                      uint32_t addr) {
    asm volatile("ldmatrix.sync.aligned.m8n8.x4.shared.b16 {%0,%1,%2,%3}, [%4];"
                 : "=r"(r0), "=r"(r1), "=r"(r2), "=r"(r3) : "r"(addr));
}
__device__ __forceinline__ void ldsm4t(uint32_t& r0, uint32_t& r1, uint32_t& r2, uint32_t& r3,
                                       uint32_t addr) {
    asm volatile("ldmatrix.sync.aligned.m8n8.x4.trans.shared.b16 {%0,%1,%2,%3}, [%4];"
                 : "=r"(r0), "=r"(r1), "=r"(r2), "=r"(r3) : "r"(addr));
}

// ---------------- streaming fp32 -> fp16 weight convert (no transpose) ----------------
// in[layer][K][N] -> out[layer][K][dstStride] at column offset colOff. grid.z = layers.
__global__ void cvt_s_kernel(const float* __restrict__ in, __half* __restrict__ out,
                             int N, int dstStride, int colOff,
                             size_t srcLayer, size_t dstLayer, int n4)
{
    int i = blockIdx.x * blockDim.x + threadIdx.x;
    if (i >= n4) return;
    in  += (size_t)blockIdx.z * srcLayer;
    out += (size_t)blockIdx.z * dstLayer;
    float4 v = ((const float4*)in)[i];
    int nv = N >> 2;
    int row = i / nv, cv = i - row * nv;
    __half2* op = (__half2*)(out + (size_t)row * dstStride + colOff + cv * 4);
    op[0] = __floats2half2_rn(v.x, v.y);
    op[1] = __floats2half2_rn(v.z, v.w);
}

// ---------------- fp32 -> fp16 convert (logits activations) ----------------
__global__ void cvt_h_kernel(const float* __restrict__ in,
                             __half* __restrict__ out, int n4)
{
    int i = blockIdx.x * blockDim.x + threadIdx.x;
    if (i >= n4) return;
    float4 v = ((const float4*)in)[i];
    __half2* op = (__half2*)(out + (size_t)i * 4);
    op[0] = __floats2half2_rn(v.x, v.y);
    op[1] = __floats2half2_rn(v.z, v.w);
}

// ---------------- bias concat kernels ----------------
__global__ void catbias3_kernel(const float* __restrict__ a, const float* __restrict__ b,
                                const float* __restrict__ c, float* __restrict__ o)
{
    int l = blockIdx.y;
    int i = blockIdx.x * 256 + threadIdx.x;
    float v;
    if (i < kD)           v = a[l * kD + i];
    else if (i < 2 * kD)  v = b[l * kD + i - kD];
    else                  v = c[l * kD + i - 2 * kD];
    o[(size_t)l * kQS + i] = v;
}
__global__ void catbias2_kernel(const float* __restrict__ a, const float* __restrict__ b,
                                float* __restrict__ o)
{
    int l = blockIdx.y;
    int i = blockIdx.x * 256 + threadIdx.x;
    float v = (i < kD2) ? a[l * kD2 + i] : b[l * kD2 + i - kD2];
    o[(size_t)l * kPU + i] = v;
}

// ---------------- embed + positional encoding ----------------
__global__ void embed_pe_kernel(const int* __restrict__ ids,
                                const float* __restrict__ embed,
                                float* __restrict__ x)
{
    int row = blockIdx.x;
    int l   = row % kL;
    int id  = ids[row];
    int d0  = threadIdx.x * 4;
    float4 ev = *(const float4*)&embed[(size_t)id * kD + d0];
    float out[4] = {ev.x, ev.y, ev.z, ev.w};
    const float negc = -0.0089944731f;   // -log(10000)/1024 in fp32
#pragma unroll
    for (int t = 0; t < 4; ++t) {
        int d  = d0 + t;
        int i2 = (d >> 1) * 2;
        float freq = expf((float)i2 * negc);
        float a    = (float)l * freq;
        out[t] += (d & 1) ? cosf(a) : sinf(a);
    }
    *(float4*)&x[(size_t)row * kD + d0] = make_float4(out[0], out[1], out[2], out[3]);
}

// ---------------- rmsnorm (emits fp16) ----------------
__global__ void rmsnorm_kernel(const float* __restrict__ x,
                               const float* __restrict__ gamma,
                               __half* __restrict__ y)
{
    int row = blockIdx.x;
    const float* xr = x + (size_t)row * kD;
    int d0 = threadIdx.x * 4;
    float4 v = *(const float4*)&xr[d0];
    float ss = v.x * v.x + v.y * v.y + v.z * v.z + v.w * v.w;
#pragma unroll
    for (int off = 16; off; off >>= 1)
        ss += __shfl_xor_sync(0xffffffffu, ss, off);
    __shared__ float ws[8];
    int lane = threadIdx.x & 31, w = threadIdx.x >> 5;
    if (lane == 0) ws[w] = ss;
    __syncthreads();
    if (w == 0) {
        float t = (lane < 8) ? ws[lane] : 0.0f;
#pragma unroll
        for (int off = 4; off; off >>= 1)
            t += __shfl_xor_sync(0xffffffffu, t, off);
        if (lane == 0) ws[0] = t;
    }
    __syncthreads();
    float scale = rsqrtf(ws[0] / (float)kD + EPSF);
    float4 g = *(const float4*)&gamma[d0];
    __half2* yp = (__half2*)&y[(size_t)row * kD + d0];
    yp[0] = __floats2half2_rn(v.x * scale * g.x, v.y * scale * g.y);
    yp[1] = __floats2half2_rn(v.z * scale * g.z, v.w * scale * g.w);
}

// ---------------- silu gate (fused fp16 proj|up input) ----------------
__global__ void silu_gate_kernel(const __half* __restrict__ pu,
                                 __half* __restrict__ gate)
{
    size_t t = ((size_t)blockIdx.x * blockDim.x + threadIdx.x) * 4;
    size_t row = t >> 11;
    int c = (int)(t & (kD2 - 1));
    const __half2* pp = (const __half2*)(pu + row * kPU + c);
    const __half2* uu = (const __half2*)(pu + row * kPU + kD2 + c);
    float2 p0 = __half22float2(pp[0]), p1 = __half22float2(pp[1]);
    float2 u0 = __half22float2(uu[0]), u1 = __half22float2(uu[1]);
    float t0 = p0.x * u0.x, t1 = p0.y * u0.y, t2 = p1.x * u1.x, t3 = p1.y * u1.y;
    float s0 = t0 / (1.0f + __expf(-t0));
    float s1 = t1 / (1.0f + __expf(-t1));
    float s2 = t2 / (1.0f + __expf(-t2));
    float s3 = t3 / (1.0f + __expf(-t3));
    __half2* gp = (__half2*)&gate[row * kD2 + c];
    gp[0] = __floats2half2_rn(s0, s1);
    gp[1] = __floats2half2_rn(s2, s3);
}

// ================= FP16 GEMM: B in natural [K][N] layout, ldsm.trans fragments =========
// A staged [128 rows][32k] pitch 40h; B staged [32k][128n] pitch 136h (conflict-free).
constexpr int kABytes = 128 * 40 * 2;      // 10240 B
constexpr int kBBytes = 32 * 136 * 2;      // 8704 B
constexpr int kBufBytes = kABytes + kBBytes;  // 18944 per stage
constexpr int kGemmSmem = 3 * kBufBytes;      // 56832

template<bool HOUT>
__global__ void __launch_bounds__(256, 2)
gemm_f16_kernel(const __half* __restrict__ A, const __half* __restrict__ Bw,
                const float* __restrict__ bias, const float* __restrict__ resid,
                void* __restrict__ Cv, int M, int N, int K)
{
    extern __shared__ char smem[];
    uint32_t base = (uint32_t)__cvta_generic_to_shared(smem);

    int tid  = threadIdx.x;
    int lane = tid & 31;
    int warp = tid >> 5;
    int wm = warp >> 2;
    int wn = warp & 3;
    int bm = blockIdx.y, bn = blockIdx.x;

    const __half* Ab = A  + (size_t)bm * 128 * K;
    const __half* Bb = Bw + (size_t)(bn * 128);   // column offset; rows stride N

    // cp.async: A 512 chunks (2/thread), B 512 chunks (2/thread)
    int arw[2], asb[2], brw[2], bsb[2];
    uint32_t dstA[2], dstB[2];
#pragma unroll
    for (int i = 0; i < 2; ++i) {
        int c = i * 256 + tid;
        arw[i] = c >> 2;  asb[i] = c & 3;            // A: row 0..127, 4x16B
        dstA[i] = base + (uint32_t)(arw[i] * 80 + asb[i] * 16);
        brw[i] = c >> 4;  bsb[i] = c & 15;           // B: row 0..31, 16x16B
        dstB[i] = base + (uint32_t)(kABytes + brw[i] * 272 + bsb[i] * 16);
    }

    int q  = lane >> 3;
    int r8 = lane & 7;
    uint32_t aAddr = base + (uint32_t)((wm * 64 + (q & 1) * 8 + r8) * 80 + (q >> 1) * 16);
    // B ldsm.trans: rows = k (within 16), cols = n (warp wn covers 32 cols)
    uint32_t bAddr = base + (uint32_t)(kABytes + ((q & 1) * 8 + r8) * 272
                                       + (wn * 32 + (q >> 1) * 8) * 2);

    float acc[4][4][4];
#pragma unroll
    for (int mt = 0; mt < 4; ++mt)
#pragma unroll
        for (int nt = 0; nt < 4; ++nt)
#pragma unroll
            for (int r = 0; r < 4; ++r) acc[mt][nt][r] = 0.0f;

    int nit = K >> 5;

    auto stage = [&](int k0, int b) {
        uint32_t boff = (uint32_t)(b * kBufBytes);
#pragma unroll
        for (int i = 0; i < 2; ++i) {
            cp16(dstA[i] + boff, &Ab[(size_t)arw[i] * K + k0 + asb[i] * 8]);
            cp16(dstB[i] + boff, &Bb[(size_t)(k0 + brw[i]) * N + bsb[i] * 8]);
        }
        asm volatile("cp.async.commit_group;");
    };

    stage(0, 0);
    if (nit > 1) stage(32, 1);

    int buf = 0;
    for (int it = 0; it < nit; ++it) {
        if (it + 1 < nit) asm volatile("cp.async.wait_group 1;");
        else              asm volatile("cp.async.wait_group 0;");
        __syncthreads();
        if (it + 2 < nit) {
            int nb = buf + 2; if (nb >= 3) nb -= 3;
            stage((it + 2) << 5, nb);
        }
        uint32_t bufoff = (uint32_t)(buf * kBufBytes);
#pragma unroll
        for (int ks = 0; ks < 2; ++ks) {
            uint32_t afr[4][4], bfr[4][2];
#pragma unroll
            for (int mt = 0; mt < 4; ++mt)
                ldsm4(afr[mt][0], afr[mt][1], afr[mt][2], afr[mt][3],
                      aAddr + bufoff + (uint32_t)(ks * 32 + mt * 16 * 80));
#pragma unroll
            for (int np = 0; np < 2; ++np) {
                uint32_t r0, r1, r2, r3;
                ldsm4t(r0, r1, r2, r3,
                       bAddr + bufoff + (uint32_t)(ks * 16 * 272 + np * 32));
                bfr[2 * np][0] = r0; bfr[2 * np][1] = r1;
                bfr[2 * np + 1][0] = r2; bfr[2 * np + 1][1] = r3;
            }
#pragma unroll
            for (int mt = 0; mt < 4; ++mt)
#pragma unroll
                for (int nt = 0; nt < 4; ++nt)
                    mma_f16(acc[mt][nt], afr[mt], bfr[nt][0], bfr[nt][1]);
        }
        if (++buf == 3) buf = 0;
    }

    int rb = bm * 128 + wm * 64 + (lane >> 2);
    int cb = bn * 128 + wn * 32 + (lane & 3) * 2;
#pragma unroll
    for (int mt = 0; mt < 4; ++mt) {
#pragma unroll
        for (int nt = 0; nt < 4; ++nt) {
            int r0 = rb + mt * 16;
            int c0 = cb + nt * 8;
            float b0 = bias[c0], b1 = bias[c0 + 1];
            size_t off0 = (size_t)r0 * N + c0;
            size_t off1 = (size_t)(r0 + 8) * N + c0;
            float v0 = acc[mt][nt][0] + b0, v1 = acc[mt][nt][1] + b1;
            float v2 = acc[mt][nt][2] + b0, v3 = acc[mt][nt][3] + b1;
            if (!HOUT) {
                float* C = (float*)Cv;
                if (resid) {
                    float2 rr0 = *(const float2*)&resid[off0];
                    float2 rr1 = *(const float2*)&resid[off1];
                    v0 += rr0.x; v1 += rr0.y; v2 += rr1.x; v3 += rr1.y;
                }
                *(float2*)&C[off0] = make_float2(v0, v1);
                *(float2*)&C[off1] = make_float2(v2, v3);
            } else {
                __half* C = (__half*)Cv;
                *(__half2*)&C[off0] = __floats2half2_rn(v0, v1);
                *(__half2*)&C[off1] = __floats2half2_rn(v2, v3);
            }
        }
    }
}

// ================= flash attention, FP16 MMA end-to-end (R13, unchanged) =================
constexpr int kKVp = 72;
constexpr int kAttnSmem = (2 * 64 * kKVp + 4 * 16 * kKVp) * 2;  // 27648 B

__global__ void __launch_bounds__(128)
flash_attn_f16(const __half* __restrict__ QKV, __half* __restrict__ O)
{
    extern __shared__ __half hsm[];
    __half* Ks = hsm;
    __half* Vs = hsm + 64 * kKVp;
    __half* Ps = hsm + 2 * 64 * kKVp + (threadIdx.x >> 5) * 16 * kKVp;
    uint32_t ksBase = (uint32_t)__cvta_generic_to_shared(Ks);
    uint32_t vsBase = (uint32_t)__cvta_generic_to_shared(Vs);

    int tid = threadIdx.x, lane = tid & 31, w = tid >> 5;
    int g = lane >> 2, tg = lane & 3;
    int q  = lane >> 3;
    int r8 = lane & 7;
    int bh = blockIdx.y;
    int b  = bh >> 4;
    int h  = bh & 15;
    int q0 = blockIdx.x * 64;
    size_t baseq = ((size_t)b * kL) * kQS + (size_t)h * kDH;
    size_t obase = ((size_t)b * kL) * kD  + (size_t)h * kDH;
    int rlo = q0 + w * 16 + g;

    uint32_t kAddr = ksBase + (uint32_t)((((q & 1) * 8 + r8) * kKVp + (q >> 1) * 8) * 2);
    uint32_t vAddr = vsBase + (uint32_t)((((q & 1) * 8 + r8) * kKVp + (q >> 1) * 8) * 2);

    uint32_t qf[4][4];
    {
        const __half* Qp = QKV + baseq + (size_t)rlo * kQS;
#pragma unroll
        for (int ks = 0; ks < 4; ++ks) {
            int kk = ks * 16 + 2 * tg;
            qf[ks][0] = *(const uint32_t*)&Qp[kk];
            qf[ks][1] = *(const uint32_t*)&Qp[(size_t)8 * kQS + kk];
            qf[ks][2] = *(const uint32_t*)&Qp[kk + 8];
            qf[ks][3] = *(const uint32_t*)&Qp[(size_t)8 * kQS + kk + 8];
        }
    }

    float of[8][4];
#pragma unroll
    for (int nt = 0; nt < 8; ++nt)
#pragma unroll
        for (int e = 0; e < 4; ++e) of[nt][e] = 0.0f;
    float mlo = -1e30f, mhi = -1e30f, llo = 0.0f, lhi = 0.0f;

    int nkt = blockIdx.x + 1;
    for (int kt = 0; kt < nkt; ++kt) {
        int k0 = kt * 64;
        __syncthreads();
#pragma unroll
        for (int i = 0; i < 4; ++i) {
            int c = i * 128 + tid;
            int row = c >> 3;
            int h8  = (c & 7) * 8;
            size_t roff = baseq + (size_t)(k0 + row) * kQS + h8;
            *(uint4*)&Ks[row * kKVp + h8] = *(const uint4*)&QKV[roff + kD];
            *(uint4*)&Vs[row * kKVp + h8] = *(const uint4*)&QKV[roff + 2 * kD];
        }
        __syncthreads();

        float s[8][4];
#pragma unroll
        for (int nt = 0; nt < 8; ++nt)
#pragma unroll
            for (int e = 0; e < 4; ++e) s[nt][e] = 0.0f;
#pragma unroll
        for (int ks = 0; ks < 4; ++ks) {
            uint32_t bfr[8][2];
#pragma unroll
            for (int np = 0; np < 4; ++np) {
                uint32_t r0, r1, r2, r3;
                ldsm4(r0, r1, r2, r3,
                      kAddr + (uint32_t)(((np * 16) * kKVp + ks * 16) * 2));
                bfr[2 * np][0] = r0; bfr[2 * np + 1][0] = r1;
                bfr[2 * np][1] = r2; bfr[2 * np + 1][1] = r3;
            }
#pragma unroll
            for (int nt = 0; nt < 8; ++nt)
                mma_f16(s[nt], qf[ks], bfr[nt][0], bfr[nt][1]);
        }

        bool diag = (kt == blockIdx.x);
        float rmlo = -1e30f, rmhi = -1e30f;
#pragma unroll
        for (int nt = 0; nt < 8; ++nt) {
#pragma unroll
            for (int e = 0; e < 4; ++e) {
                float v = s[nt][e] * 0.125f;
                if (diag) {
                    int key = k0 + nt * 8 + 2 * tg + (e & 1);
                    int row = (e < 2) ? rlo : rlo + 8;
                    if (key > row) v = -1e30f;
                }
                s[nt][e] = v;
                if (e < 2) rmlo = fmaxf(rmlo, v); else rmhi = fmaxf(rmhi, v);
            }
        }
        rmlo = fmaxf(rmlo, __shfl_xor_sync(0xffffffffu, rmlo, 1));
        rmlo = fmaxf(rmlo, __shfl_xor_sync(0xffffffffu, rmlo, 2));
        rmhi = fmaxf(rmhi, __shfl_xor_sync(0xffffffffu, rmhi, 1));
        rmhi = fmaxf(rmhi, __shfl_xor_sync(0xffffffffu, rmhi, 2));
        float mnlo = fmaxf(mlo, rmlo), mnhi = fmaxf(mhi, rmhi);
        float clo = __expf(mlo - mnlo), chi = __expf(mhi - mnhi);
        mlo = mnlo; mhi = mnhi;

        float rslo = 0.0f, rshi = 0.0f;
#pragma unroll
        for (int nt = 0; nt < 8; ++nt) {
            float p0 = __expf(s[nt][0] - mlo);
            float p1 = __expf(s[nt][1] - mlo);
            float p2 = __expf(s[nt][2] - mhi);
            float p3 = __expf(s[nt][3] - mhi);
            rslo += p0 + p1; rshi += p2 + p3;
            int col = nt * 8 + 2 * tg;
            *(__half2*)&Ps[g * kKVp + col]       = __floats2half2_rn(p0, p1);
            *(__half2*)&Ps[(g + 8) * kKVp + col] = __floats2half2_rn(p2, p3);
        }
        rslo += __shfl_xor_sync(0xffffffffu, rslo, 1);
        rslo += __shfl_xor_sync(0xffffffffu, rslo, 2);
        rshi += __shfl_xor_sync(0xffffffffu, rshi, 1);
        rshi += __shfl_xor_sync(0xffffffffu, rshi, 2);
        llo = llo * clo + rslo;
        lhi = lhi * chi + rshi;
#pragma unroll
        for (int nt = 0; nt < 8; ++nt) {
            of[nt][0] *= clo; of[nt][1] *= clo;
            of[nt][2] *= chi; of[nt][3] *= chi;
        }
        __syncwarp();

#pragma unroll
        for (int ks = 0; ks < 4; ++ks) {
            int kk = ks * 16;
            uint32_t pa[4];
            pa[0] = *(const uint32_t*)&Ps[g * kKVp + kk + 2 * tg];
            pa[1] = *(const uint32_t*)&Ps[(g + 8) * kKVp + kk + 2 * tg];
            pa[2] = *(const uint32_t*)&Ps[g * kKVp + kk + 8 + 2 * tg];
            pa[3] = *(const uint32_t*)&Ps[(g + 8) * kKVp + kk + 8 + 2 * tg];
            uint32_t bfr[8][2];
#pragma unroll
            for (int np = 0; np < 4; ++np) {
                uint32_t r0, r1, r2, r3;
                ldsm4t(r0, r1, r2, r3,
                       vAddr + (uint32_t)((kk * kKVp + np * 16) * 2));
                bfr[2 * np][0] = r0; bfr[2 * np][1] = r1;
                bfr[2 * np + 1][0] = r2; bfr[2 * np + 1][1] = r3;
            }
#pragma unroll
            for (int nt = 0; nt < 8; ++nt)
                mma_f16(of[nt], pa, bfr[nt][0], bfr[nt][1]);
        }
        __syncwarp();
    }

    float ilo = 1.0f / llo, ihi = 1.0f / lhi;
#pragma unroll
    for (int nt = 0; nt < 8; ++nt) {
        int col = nt * 8 + 2 * tg;
        size_t off0 = obase + (size_t)rlo * kD + col;
        size_t off1 = obase + (size_t)(rlo + 8) * kD + col;
        *(__half2*)&O[off0] = __floats2half2_rn(of[nt][0] * ilo, of[nt][1] * ilo);
        *(__half2*)&O[off1] = __floats2half2_rn(of[nt][2] * ihi, of[nt][3] * ihi);
    }
}

// ---------------- host launcher ----------------
static void launch_gemm_f(const __half* A, const __half* Bw, const float* bias,
                          const float* resid, float* C, int M, int N, int K)
{
    dim3 grid(N / 128, M / 128);
    gemm_f16_kernel<false><<<grid, 256, kGemmSmem>>>(A, Bw, bias, resid, C, M, N, K);
}
static void launch_gemm_h(const __half* A, const __half* Bw, const float* bias,
                          __half* C, int M, int N, int K)
{
    dim3 grid(N / 128, M / 128);
    gemm_f16_kernel<true><<<grid, 256, kGemmSmem>>>(A, Bw, bias, nullptr, C, M, N, K);
}
static void launch_cvt_s(const float* in, __half* out, int K, int N,
                         int dstStride, int colOff, int layers,
                         size_t srcLayer, size_t dstLayer)
{
    int n4 = (K * N) / 4;
    dim3 grid((n4 + 255) / 256, 1, layers);
    cvt_s_kernel<<<grid, 256>>>(in, out, N, dstStride, colOff, srcLayer, dstLayer, n4);
}

extern "C" void kernel_launch(void* const* d_in, const int* in_sizes, int n_in,
                              void* d_out, int out_size)
{
    const int*   ids    = (const int*)  d_in[0];
    const float* embed  = (const float*)d_in[1];
    const float* Wq     = (const float*)d_in[2];
    const float* bq     = (const float*)d_in[3];
    const float* Wk     = (const float*)d_in[4];
    const float* bk     = (const float*)d_in[5];
    const float* Wv     = (const float*)d_in[6];
    const float* bv     = (const float*)d_in[7];
    const float* Wo     = (const float*)d_in[8];
    const float* bo     = (const float*)d_in[9];
    const float* Wproj  = (const float*)d_in[10];
    const float* bproj  = (const float*)d_in[11];
    const float* Wup    = (const float*)d_in[12];
    const float* bup    = (const float*)d_in[13];
    const float* Wdown  = (const float*)d_in[14];
    const float* bdown  = (const float*)d_in[15];
    const float* gammas = (const float*)d_in[16];
    const float* Wlog   = (const float*)d_in[17];
    const float* blog   = (const float*)d_in[18];
    float* out = (float*)d_out;

    float *x, *bqkv, *bpu;
    __half *qkv, *pu, *h, *att, *gate, *wh;
    cudaGetSymbolAddress((void**)&x,    g_x);
    cudaGetSymbolAddress((void**)&qkv,  g_qkv);
    cudaGetSymbolAddress((void**)&pu,   g_pu);
    cudaGetSymbolAddress((void**)&bqkv, g_bqkv);
    cudaGetSymbolAddress((void**)&bpu,  g_bpu);
    cudaGetSymbolAddress((void**)&h,    g_h);
    cudaGetSymbolAddress((void**)&att,  g_att);
    cudaGetSymbolAddress((void**)&gate, g_gate);
    cudaGetSymbolAddress((void**)&wh,   g_wh);

    cudaFuncSetAttribute(gemm_f16_kernel<false>,
                         cudaFuncAttributeMaxDynamicSharedMemorySize, kGemmSmem);
    cudaFuncSetAttribute(gemm_f16_kernel<true>,
                         cudaFuncAttributeMaxDynamicSharedMemorySize, kGemmSmem);

    // streaming weight convert into natural [K][N] fused layouts (8 launches)
    launch_cvt_s(Wq,    wh + qkvOff(0), kD,  kD,  kQS, 0,        kNL, kDD,     3 * kDD);
    launch_cvt_s(Wk,    wh + qkvOff(0), kD,  kD,  kQS, kD,       kNL, kDD,     3 * kDD);
    launch_cvt_s(Wv,    wh + qkvOff(0), kD,  kD,  kQS, 2 * kD,   kNL, kDD,     3 * kDD);
    launch_cvt_s(Wo,    wh + kWoBase,   kD,  kD,  kD,  0,        kNL, kDD,     kDD);
    launch_cvt_s(Wproj, wh + kPuBase,   kD,  kD2, kPU, 0,        kNL, 2 * kDD, 4 * kDD);
    launch_cvt_s(Wup,   wh + kPuBase,   kD,  kD2, kPU, kD2,      kNL, 2 * kDD, 4 * kDD);
    launch_cvt_s(Wdown, wh + kDnBase,   kD2, kD,  kD,  0,        kNL, 2 * kDD, 2 * kDD);
    launch_cvt_s(Wlog,  wh + kLgBase,   kD,  kV,  kV,  0,        1,   0,       0);

    catbias3_kernel<<<dim3(kQS / 256, kNL), 256>>>(bq, bk, bv, bqkv);
    catbias2_kernel<<<dim3(kPU / 256, kNL), 256>>>(bproj, bup, bpu);

    embed_pe_kernel<<<kBL, 256>>>(ids, embed, x);

    for (int i = 0; i < kNL; ++i) {
        rmsnorm_kernel<<<kBL, 256>>>(x, gammas + (size_t)(2 * i) * kD, h);
        launch_gemm_h(h, wh + qkvOff(i), bqkv + (size_t)i * kQS, qkv, kBL, kQS, kD);
        flash_attn_f16<<<dim3(kL / 64, kB * kH), 128, kAttnSmem>>>(qkv, att);
        launch_gemm_f(att, wh + woOff(i), bo + (size_t)i * kD, x, x, kBL, kD, kD);
        rmsnorm_kernel<<<kBL, 256>>>(x, gammas + (size_t)(2 * i + 1) * kD, h);
        launch_gemm_h(h, wh + puOff(i), bpu + (size_t)i * kPU, pu, kBL, kPU, kD);
        silu_gate_kernel<<<((size_t)kBL * kD2) / (256 * 4), 256>>>(pu, gate);
        launch_gemm_f(gate, wh + dnOff(i), bdown + (size_t)i * kD, x, x, kBL, kD, kD2);
    }
    int n4 = (kBL * kD) / 4;
    cvt_h_kernel<<<(n4 + 255) / 256, 256>>>(x, h, n4);
    launch_gemm_f(h, wh + kLgBase, blog, nullptr, out, kBL, kV, kD);
}

// round 16
// speedup vs baseline: 1.4813x; 1.0394x over previous
#include <cuda_runtime.h>
#include <cuda_fp16.h>
#include <math.h>
#include <stdint.h>

// ---------------- problem constants ----------------
constexpr int kNL = 4;
constexpr int kD  = 1024;
constexpr int kD2 = 2048;
constexpr int kH  = 16;
constexpr int kDH = 64;
constexpr int kV  = 32000;
constexpr int kB  = 2;
constexpr int kL  = 2048;
constexpr int kBL = kB * kL;   // 4096
constexpr int kQS = 3 * kD;    // fused qkv row stride (3072)
constexpr int kPU = 2 * kD2;   // fused proj/up row stride (4096)
#define EPSF 1e-6f

// ---------------- scratch (device globals; no allocation allowed) ----------------
__device__ __align__(1024) float  g_x[kBL * kD];                  // residual (fp32)
__device__ __align__(1024) __half g_qkv[(size_t)kBL * kQS];       // fused q|k|v (fp16)
__device__ __align__(1024) __half g_pu[(size_t)kBL * kPU];        // fused proj|up (fp16)
__device__ __align__(1024) __half g_h[kBL * kD];                  // rmsnorm out / logits A
__device__ __align__(1024) __half g_att[kBL * kD];                // attention out
__device__ __align__(1024) __half g_gate[(size_t)kBL * kD2];      // silu out
__device__ __align__(1024) float  g_bqkv[kNL * kQS];              // fused qkv bias
__device__ __align__(1024) float  g_bpu[kNL * kPU];               // fused proj/up bias

// fp16 weights in NATURAL [K][N] layout (fused along N). Per-layer blocks.
constexpr size_t kDD = (size_t)kD * kD;                 // 1M
__device__ __forceinline__ __host__ size_t qkvOff(int i) { return (size_t)i * 3 * kDD; }
constexpr size_t kWoBase = (size_t)kNL * 3 * kDD;       // 12M
__device__ __forceinline__ __host__ size_t woOff(int i)  { return kWoBase + (size_t)i * kDD; }
constexpr size_t kPuBase = kWoBase + (size_t)kNL * kDD; // 16M
__device__ __forceinline__ __host__ size_t puOff(int i)  { return kPuBase + (size_t)i * 4 * kDD; }
constexpr size_t kDnBase = kPuBase + (size_t)kNL * 4 * kDD; // 32M
__device__ __forceinline__ __host__ size_t dnOff(int i)  { return kDnBase + (size_t)i * 2 * kDD; }
constexpr size_t kLgBase = kDnBase + (size_t)kNL * 2 * kDD; // 40M
constexpr size_t kWTot = kLgBase + (size_t)kD * kV;         // 72.768M
__device__ __align__(1024) __half g_wh[kWTot];

// ---------------- small helpers ----------------
__device__ __forceinline__ void mma_f16(float* c, const uint32_t* a, uint32_t b0, uint32_t b1) {
    asm volatile(
        "mma.sync.aligned.m16n8k16.row.col.f32.f16.f16.f32 "
        "{%0,%1,%2,%3}, {%4,%5,%6,%7}, {%8,%9}, {%0,%1,%2,%3};"
        : "+f"(c[0]), "+f"(c[1]), "+f"(c[2]), "+f"(c[3])
        : "r"(a[0]), "r"(a[1]), "r"(a[2]), "r"(a[3]), "r"(b0), "r"(b1));
}
__device__ __forceinline__ void cp16(uint32_t dst, const void* src) {
    asm volatile("cp.async.cg.shared.global [%0], [%1], 16;" :: "r"(dst), "l"(src));
}
__device__ __forceinline__ void ldsm4(uint32_t& r0, uint32_t& r1, uint32_t& r2, uint32_t& r3,
                                      uint32_t addr) {
    asm volatile("ldmatrix.sync.aligned.m8n8.x4.shared.b16 {%0,%1,%2,%3}, [%4];"
                 : "=r"(r0), "=r"(r1), "=r"(r2), "=r"(r3) : "r"(addr));
}
__device__ __forceinline__ void ldsm4t(uint32_t& r0, uint32_t& r1, uint32_t& r2, uint32_t& r3,
                                       uint32_t addr) {
    asm volatile("ldmatrix.sync.aligned.m8n8.x4.trans.shared.b16 {%0,%1,%2,%3}, [%4];"
                 : "=r"(r0), "=r"(r1), "=r"(r2), "=r"(r3) : "r"(addr));
}

// ---------------- streaming fp32 -> fp16 weight convert (no transpose) ----------------
__global__ void cvt_s_kernel(const float* __restrict__ in, __half* __restrict__ out,
                             int N, int dstStride, int colOff,
                             size_t srcLayer, size_t dstLayer, int n4)
{
    int i = blockIdx.x * blockDim.x + threadIdx.x;
    if (i >= n4) return;
    in  += (size_t)blockIdx.z * srcLayer;
    out += (size_t)blockIdx.z * dstLayer;
    float4 v = ((const float4*)in)[i];
    int nv = N >> 2;
    int row = i / nv, cv = i - row * nv;
    __half2* op = (__half2*)(out + (size_t)row * dstStride + colOff + cv * 4);
    op[0] = __floats2half2_rn(v.x, v.y);
    op[1] = __floats2half2_rn(v.z, v.w);
}

// ---------------- fp32 -> fp16 convert (logits activations) ----------------
__global__ void cvt_h_kernel(const float* __restrict__ in,
                             __half* __restrict__ out, int n4)
{
    int i = blockIdx.x * blockDim.x + threadIdx.x;
    if (i >= n4) return;
    float4 v = ((const float4*)in)[i];
    __half2* op = (__half2*)(out + (size_t)i * 4);
    op[0] = __floats2half2_rn(v.x, v.y);
    op[1] = __floats2half2_rn(v.z, v.w);
}

// ---------------- bias concat kernels ----------------
__global__ void catbias3_kernel(const float* __restrict__ a, const float* __restrict__ b,
                                const float* __restrict__ c, float* __restrict__ o)
{
    int l = blockIdx.y;
    int i = blockIdx.x * 256 + threadIdx.x;
    float v;
    if (i < kD)           v = a[l * kD + i];
    else if (i < 2 * kD)  v = b[l * kD + i - kD];
    else                  v = c[l * kD + i - 2 * kD];
    o[(size_t)l * kQS + i] = v;
}
__global__ void catbias2_kernel(const float* __restrict__ a, const float* __restrict__ b,
                                float* __restrict__ o)
{
    int l = blockIdx.y;
    int i = blockIdx.x * 256 + threadIdx.x;
    float v = (i < kD2) ? a[l * kD2 + i] : b[l * kD2 + i - kD2];
    o[(size_t)l * kPU + i] = v;
}

// ---------------- embed + positional encoding ----------------
__global__ void embed_pe_kernel(const int* __restrict__ ids,
                                const float* __restrict__ embed,
                                float* __restrict__ x)
{
    int row = blockIdx.x;
    int l   = row % kL;
    int id  = ids[row];
    int d0  = threadIdx.x * 4;
    float4 ev = *(const float4*)&embed[(size_t)id * kD + d0];
    float out[4] = {ev.x, ev.y, ev.z, ev.w};
    const float negc = -0.0089944731f;   // -log(10000)/1024 in fp32
#pragma unroll
    for (int t = 0; t < 4; ++t) {
        int d  = d0 + t;
        int i2 = (d >> 1) * 2;
        float freq = expf((float)i2 * negc);
        float a    = (float)l * freq;
        out[t] += (d & 1) ? cosf(a) : sinf(a);
    }
    *(float4*)&x[(size_t)row * kD + d0] = make_float4(out[0], out[1], out[2], out[3]);
}

// ---------------- rmsnorm (emits fp16) ----------------
__global__ void rmsnorm_kernel(const float* __restrict__ x,
                               const float* __restrict__ gamma,
                               __half* __restrict__ y)
{
    int row = blockIdx.x;
    const float* xr = x + (size_t)row * kD;
    int d0 = threadIdx.x * 4;
    float4 v = *(const float4*)&xr[d0];
    float ss = v.x * v.x + v.y * v.y + v.z * v.z + v.w * v.w;
#pragma unroll
    for (int off = 16; off; off >>= 1)
        ss += __shfl_xor_sync(0xffffffffu, ss, off);
    __shared__ float ws[8];
    int lane = threadIdx.x & 31, w = threadIdx.x >> 5;
    if (lane == 0) ws[w] = ss;
    __syncthreads();
    if (w == 0) {
        float t = (lane < 8) ? ws[lane] : 0.0f;
#pragma unroll
        for (int off = 4; off; off >>= 1)
            t += __shfl_xor_sync(0xffffffffu, t, off);
        if (lane == 0) ws[0] = t;
    }
    __syncthreads();
    float scale = rsqrtf(ws[0] / (float)kD + EPSF);
    float4 g = *(const float4*)&gamma[d0];
    __half2* yp = (__half2*)&y[(size_t)row * kD + d0];
    yp[0] = __floats2half2_rn(v.x * scale * g.x, v.y * scale * g.y);
    yp[1] = __floats2half2_rn(v.z * scale * g.z, v.w * scale * g.w);
}

// ---------------- silu gate (fused fp16 proj|up input) ----------------
__global__ void silu_gate_kernel(const __half* __restrict__ pu,
                                 __half* __restrict__ gate)
{
    size_t t = ((size_t)blockIdx.x * blockDim.x + threadIdx.x) * 4;
    size_t row = t >> 11;
    int c = (int)(t & (kD2 - 1));
    const __half2* pp = (const __half2*)(pu + row * kPU + c);
    const __half2* uu = (const __half2*)(pu + row * kPU + kD2 + c);
    float2 p0 = __half22float2(pp[0]), p1 = __half22float2(pp[1]);
    float2 u0 = __half22float2(uu[0]), u1 = __half22float2(uu[1]);
    float t0 = p0.x * u0.x, t1 = p0.y * u0.y, t2 = p1.x * u1.x, t3 = p1.y * u1.y;
    float s0 = t0 / (1.0f + __expf(-t0));
    float s1 = t1 / (1.0f + __expf(-t1));
    float s2 = t2 / (1.0f + __expf(-t2));
    float s3 = t3 / (1.0f + __expf(-t3));
    __half2* gp = (__half2*)&gate[row * kD2 + c];
    gp[0] = __floats2half2_rn(s0, s1);
    gp[1] = __floats2half2_rn(s2, s3);
}

// ================= FP16 GEMM: K-64 chunks, B natural [K][N], ldsm.trans =================
// A staged [128 rows][64k] pitch 72h; B staged [64k][128n] pitch 136h.
constexpr int kABytes = 128 * 72 * 2;      // 18432 B
constexpr int kBBytes = 64 * 136 * 2;      // 17408 B
constexpr int kBufBytes = kABytes + kBBytes;  // 35840 per stage
constexpr int kGemmSmem = 3 * kBufBytes;      // 107520

template<bool HOUT>
__global__ void __launch_bounds__(256, 2)
gemm_f16_kernel(const __half* __restrict__ A, const __half* __restrict__ Bw,
                const float* __restrict__ bias, const float* __restrict__ resid,
                void* __restrict__ Cv, int M, int N, int K)
{
    extern __shared__ char smem[];
    uint32_t base = (uint32_t)__cvta_generic_to_shared(smem);

    int tid  = threadIdx.x;
    int lane = tid & 31;
    int warp = tid >> 5;
    int wm = warp >> 2;
    int wn = warp & 3;
    int bm = blockIdx.y, bn = blockIdx.x;

    const __half* Ab = A  + (size_t)bm * 128 * K;
    const __half* Bb = Bw + (size_t)(bn * 128);   // column offset; rows stride N

    // cp.async: A 1024 chunks (4/thread), B 1024 chunks (4/thread)
    int arw[4], asb[4], brw[4], bsb[4];
    uint32_t dstA[4], dstB[4];
#pragma unroll
    for (int i = 0; i < 4; ++i) {
        int c = i * 256 + tid;
        arw[i] = c >> 3;  asb[i] = c & 7;            // A: row 0..127, 8x16B
        dstA[i] = base + (uint32_t)(arw[i] * 144 + asb[i] * 16);
        brw[i] = c >> 4;  bsb[i] = c & 15;           // B: row 0..63, 16x16B
        dstB[i] = base + (uint32_t)(kABytes + brw[i] * 272 + bsb[i] * 16);
    }

    int q  = lane >> 3;
    int r8 = lane & 7;
    uint32_t aAddr = base + (uint32_t)((wm * 64 + (q & 1) * 8 + r8) * 144 + (q >> 1) * 16);
    uint32_t bAddr = base + (uint32_t)(kABytes + ((q & 1) * 8 + r8) * 272
                                       + (wn * 32 + (q >> 1) * 8) * 2);

    float acc[4][4][4];
#pragma unroll
    for (int mt = 0; mt < 4; ++mt)
#pragma unroll
        for (int nt = 0; nt < 4; ++nt)
#pragma unroll
            for (int r = 0; r < 4; ++r) acc[mt][nt][r] = 0.0f;

    int nit = K >> 6;   // K-64 chunks

    auto stage = [&](int k0, int b) {
        uint32_t boff = (uint32_t)(b * kBufBytes);
#pragma unroll
        for (int i = 0; i < 4; ++i) {
            cp16(dstA[i] + boff, &Ab[(size_t)arw[i] * K + k0 + asb[i] * 8]);
            cp16(dstB[i] + boff, &Bb[(size_t)(k0 + brw[i]) * N + bsb[i] * 8]);
        }
        asm volatile("cp.async.commit_group;");
    };

    stage(0, 0);
    if (nit > 1) stage(64, 1);

    int buf = 0;
    for (int it = 0; it < nit; ++it) {
        if (it + 1 < nit) asm volatile("cp.async.wait_group 1;");
        else              asm volatile("cp.async.wait_group 0;");
        __syncthreads();
        if (it + 2 < nit) {
            int nb = buf + 2; if (nb >= 3) nb -= 3;
            stage((it + 2) << 6, nb);
        }
        uint32_t bufoff = (uint32_t)(buf * kBufBytes);
#pragma unroll
        for (int ks = 0; ks < 4; ++ks) {             // 4 k16-steps per chunk
            uint32_t afr[4][4], bfr[4][2];
#pragma unroll
            for (int mt = 0; mt < 4; ++mt)
                ldsm4(afr[mt][0], afr[mt][1], afr[mt][2], afr[mt][3],
                      aAddr + bufoff + (uint32_t)(ks * 32 + mt * 16 * 144));
#pragma unroll
            for (int np = 0; np < 2; ++np) {
                uint32_t r0, r1, r2, r3;
                ldsm4t(r0, r1, r2, r3,
                       bAddr + bufoff + (uint32_t)(ks * 16 * 272 + np * 32));
                bfr[2 * np][0] = r0; bfr[2 * np][1] = r1;
                bfr[2 * np + 1][0] = r2; bfr[2 * np + 1][1] = r3;
            }
#pragma unroll
            for (int mt = 0; mt < 4; ++mt)
#pragma unroll
                for (int nt = 0; nt < 4; ++nt)
                    mma_f16(acc[mt][nt], afr[mt], bfr[nt][0], bfr[nt][1]);
        }
        if (++buf == 3) buf = 0;
    }

    int rb = bm * 128 + wm * 64 + (lane >> 2);
    int cb = bn * 128 + wn * 32 + (lane & 3) * 2;
#pragma unroll
    for (int mt = 0; mt < 4; ++mt) {
#pragma unroll
        for (int nt = 0; nt < 4; ++nt) {
            int r0 = rb + mt * 16;
            int c0 = cb + nt * 8;
            float b0 = bias[c0], b1 = bias[c0 + 1];
            size_t off0 = (size_t)r0 * N + c0;
            size_t off1 = (size_t)(r0 + 8) * N + c0;
            float v0 = acc[mt][nt][0] + b0, v1 = acc[mt][nt][1] + b1;
            float v2 = acc[mt][nt][2] + b0, v3 = acc[mt][nt][3] + b1;
            if (!HOUT) {
                float* C = (float*)Cv;
                if (resid) {
                    float2 rr0 = *(const float2*)&resid[off0];
                    float2 rr1 = *(const float2*)&resid[off1];
                    v0 += rr0.x; v1 += rr0.y; v2 += rr1.x; v3 += rr1.y;
                }
                *(float2*)&C[off0] = make_float2(v0, v1);
                *(float2*)&C[off1] = make_float2(v2, v3);
            } else {
                __half* C = (__half*)Cv;
                *(__half2*)&C[off0] = __floats2half2_rn(v0, v1);
                *(__half2*)&C[off1] = __floats2half2_rn(v2, v3);
            }
        }
    }
}

// ================= flash attention, FP16 MMA end-to-end (R13, unchanged) =================
constexpr int kKVp = 72;
constexpr int kAttnSmem = (2 * 64 * kKVp + 4 * 16 * kKVp) * 2;  // 27648 B

__global__ void __launch_bounds__(128)
flash_attn_f16(const __half* __restrict__ QKV, __half* __restrict__ O)
{
    extern __shared__ __half hsm[];
    __half* Ks = hsm;
    __half* Vs = hsm + 64 * kKVp;
    __half* Ps = hsm + 2 * 64 * kKVp + (threadIdx.x >> 5) * 16 * kKVp;
    uint32_t ksBase = (uint32_t)__cvta_generic_to_shared(Ks);
    uint32_t vsBase = (uint32_t)__cvta_generic_to_shared(Vs);

    int tid = threadIdx.x, lane = tid & 31, w = tid >> 5;
    int g = lane >> 2, tg = lane & 3;
    int q  = lane >> 3;
    int r8 = lane & 7;
    int bh = blockIdx.y;
    int b  = bh >> 4;
    int h  = bh & 15;
    int q0 = blockIdx.x * 64;
    size_t baseq = ((size_t)b * kL) * kQS + (size_t)h * kDH;
    size_t obase = ((size_t)b * kL) * kD  + (size_t)h * kDH;
    int rlo = q0 + w * 16 + g;

    uint32_t kAddr = ksBase + (uint32_t)((((q & 1) * 8 + r8) * kKVp + (q >> 1) * 8) * 2);
    uint32_t vAddr = vsBase + (uint32_t)((((q & 1) * 8 + r8) * kKVp + (q >> 1) * 8) * 2);

    uint32_t qf[4][4];
    {
        const __half* Qp = QKV + baseq + (size_t)rlo * kQS;
#pragma unroll
        for (int ks = 0; ks < 4; ++ks) {
            int kk = ks * 16 + 2 * tg;
            qf[ks][0] = *(const uint32_t*)&Qp[kk];
            qf[ks][1] = *(const uint32_t*)&Qp[(size_t)8 * kQS + kk];
            qf[ks][2] = *(const uint32_t*)&Qp[kk + 8];
            qf[ks][3] = *(const uint32_t*)&Qp[(size_t)8 * kQS + kk + 8];
        }
    }

    float of[8][4];
#pragma unroll
    for (int nt = 0; nt < 8; ++nt)
#pragma unroll
        for (int e = 0; e < 4; ++e) of[nt][e] = 0.0f;
    float mlo = -1e30f, mhi = -1e30f, llo = 0.0f, lhi = 0.0f;

    int nkt = blockIdx.x + 1;
    for (int kt = 0; kt < nkt; ++kt) {
        int k0 = kt * 64;
        __syncthreads();
#pragma unroll
        for (int i = 0; i < 4; ++i) {
            int c = i * 128 + tid;
            int row = c >> 3;
            int h8  = (c & 7) * 8;
            size_t roff = baseq + (size_t)(k0 + row) * kQS + h8;
            *(uint4*)&Ks[row * kKVp + h8] = *(const uint4*)&QKV[roff + kD];
            *(uint4*)&Vs[row * kKVp + h8] = *(const uint4*)&QKV[roff + 2 * kD];
        }
        __syncthreads();

        float s[8][4];
#pragma unroll
        for (int nt = 0; nt < 8; ++nt)
#pragma unroll
            for (int e = 0; e < 4; ++e) s[nt][e] = 0.0f;
#pragma unroll
        for (int ks = 0; ks < 4; ++ks) {
            uint32_t bfr[8][2];
#pragma unroll
            for (int np = 0; np < 4; ++np) {
                uint32_t r0, r1, r2, r3;
                ldsm4(r0, r1, r2, r3,
                      kAddr + (uint32_t)(((np * 16) * kKVp + ks * 16) * 2));
                bfr[2 * np][0] = r0; bfr[2 * np + 1][0] = r1;
                bfr[2 * np][1] = r2; bfr[2 * np + 1][1] = r3;
            }
#pragma unroll
            for (int nt = 0; nt < 8; ++nt)
                mma_f16(s[nt], qf[ks], bfr[nt][0], bfr[nt][1]);
        }

        bool diag = (kt == blockIdx.x);
        float rmlo = -1e30f, rmhi = -1e30f;
#pragma unroll
        for (int nt = 0; nt < 8; ++nt) {
#pragma unroll
            for (int e = 0; e < 4; ++e) {
                float v = s[nt][e] * 0.125f;
                if (diag) {
                    int key = k0 + nt * 8 + 2 * tg + (e & 1);
                    int row = (e < 2) ? rlo : rlo + 8;
                    if (key > row) v = -1e30f;
                }
                s[nt][e] = v;
                if (e < 2) rmlo = fmaxf(rmlo, v); else rmhi = fmaxf(rmhi, v);
            }
        }
        rmlo = fmaxf(rmlo, __shfl_xor_sync(0xffffffffu, rmlo, 1));
        rmlo = fmaxf(rmlo, __shfl_xor_sync(0xffffffffu, rmlo, 2));
        rmhi = fmaxf(rmhi, __shfl_xor_sync(0xffffffffu, rmhi, 1));
        rmhi = fmaxf(rmhi, __shfl_xor_sync(0xffffffffu, rmhi, 2));
        float mnlo = fmaxf(mlo, rmlo), mnhi = fmaxf(mhi, rmhi);
        float clo = __expf(mlo - mnlo), chi = __expf(mhi - mnhi);
        mlo = mnlo; mhi = mnhi;

        float rslo = 0.0f, rshi = 0.0f;
#pragma unroll
        for (int nt = 0; nt < 8; ++nt) {
            float p0 = __expf(s[nt][0] - mlo);
            float p1 = __expf(s[nt][1] - mlo);
            float p2 = __expf(s[nt][2] - mhi);
            float p3 = __expf(s[nt][3] - mhi);
            rslo += p0 + p1; rshi += p2 + p3;
            int col = nt * 8 + 2 * tg;
            *(__half2*)&Ps[g * kKVp + col]       = __floats2half2_rn(p0, p1);
            *(__half2*)&Ps[(g + 8) * kKVp + col] = __floats2half2_rn(p2, p3);
        }
        rslo += __shfl_xor_sync(0xffffffffu, rslo, 1);
        rslo += __shfl_xor_sync(0xffffffffu, rslo, 2);
        rshi += __shfl_xor_sync(0xffffffffu, rshi, 1);
        rshi += __shfl_xor_sync(0xffffffffu, rshi, 2);
        llo = llo * clo + rslo;
        lhi = lhi * chi + rshi;
#pragma unroll
        for (int nt = 0; nt < 8; ++nt) {
            of[nt][0] *= clo; of[nt][1] *= clo;
            of[nt][2] *= chi; of[nt][3] *= chi;
        }
        __syncwarp();

#pragma unroll
        for (int ks = 0; ks < 4; ++ks) {
            int kk = ks * 16;
            uint32_t pa[4];
            pa[0] = *(const uint32_t*)&Ps[g * kKVp + kk + 2 * tg];
            pa[1] = *(const uint32_t*)&Ps[(g + 8) * kKVp + kk + 2 * tg];
            pa[2] = *(const uint32_t*)&Ps[g * kKVp + kk + 8 + 2 * tg];
            pa[3] = *(const uint32_t*)&Ps[(g + 8) * kKVp + kk + 8 + 2 * tg];
            uint32_t bfr[8][2];
#pragma unroll
            for (int np = 0; np < 4; ++np) {
                uint32_t r0, r1, r2, r3;
                ldsm4t(r0, r1, r2, r3,
                       vAddr + (uint32_t)((kk * kKVp + np * 16) * 2));
                bfr[2 * np][0] = r0; bfr[2 * np][1] = r1;
                bfr[2 * np + 1][0] = r2; bfr[2 * np + 1][1] = r3;
            }
#pragma unroll
            for (int nt = 0; nt < 8; ++nt)
                mma_f16(of[nt], pa, bfr[nt][0], bfr[nt][1]);
        }
        __syncwarp();
    }

    float ilo = 1.0f / llo, ihi = 1.0f / lhi;
#pragma unroll
    for (int nt = 0; nt < 8; ++nt) {
        int col = nt * 8 + 2 * tg;
        size_t off0 = obase + (size_t)rlo * kD + col;
        size_t off1 = obase + (size_t)(rlo + 8) * kD + col;
        *(__half2*)&O[off0] = __floats2half2_rn(of[nt][0] * ilo, of[nt][1] * ilo);
        *(__half2*)&O[off1] = __floats2half2_rn(of[nt][2] * ihi, of[nt][3] * ihi);
    }
}

// ---------------- host launcher ----------------
static void launch_gemm_f(const __half* A, const __half* Bw, const float* bias,
                          const float* resid, float* C, int M, int N, int K)
{
    dim3 grid(N / 128, M / 128);
    gemm_f16_kernel<false><<<grid, 256, kGemmSmem>>>(A, Bw, bias, resid, C, M, N, K);
}
static void launch_gemm_h(const __half* A, const __half* Bw, const float* bias,
                          __half* C, int M, int N, int K)
{
    dim3 grid(N / 128, M / 128);
    gemm_f16_kernel<true><<<grid, 256, kGemmSmem>>>(A, Bw, bias, nullptr, C, M, N, K);
}
static void launch_cvt_s(const float* in, __half* out, int K, int N,
                         int dstStride, int colOff, int layers,
                         size_t srcLayer, size_t dstLayer)
{
    int n4 = (K * N) / 4;
    dim3 grid((n4 + 255) / 256, 1, layers);
    cvt_s_kernel<<<grid, 256>>>(in, out, N, dstStride, colOff, srcLayer, dstLayer, n4);
}

extern "C" void kernel_launch(void* const* d_in, const int* in_sizes, int n_in,
                              void* d_out, int out_size)
{
    const int*   ids    = (const int*)  d_in[0];
    const float* embed  = (const float*)d_in[1];
    const float* Wq     = (const float*)d_in[2];
    const float* bq     = (const float*)d_in[3];
    const float* Wk     = (const float*)d_in[4];
    const float* bk     = (const float*)d_in[5];
    const float* Wv     = (const float*)d_in[6];
    const float* bv     = (const float*)d_in[7];
    const float* Wo     = (const float*)d_in[8];
    const float* bo     = (const float*)d_in[9];
    const float* Wproj  = (const float*)d_in[10];
    const float* bproj  = (const float*)d_in[11];
    const float* Wup    = (const float*)d_in[12];
    const float* bup    = (const float*)d_in[13];
    const float* Wdown  = (const float*)d_in[14];
    const float* bdown  = (const float*)d_in[15];
    const float* gammas = (const float*)d_in[16];
    const float* Wlog   = (const float*)d_in[17];
    const float* blog   = (const float*)d_in[18];
    float* out = (float*)d_out;

    float *x, *bqkv, *bpu;
    __half *qkv, *pu, *h, *att, *gate, *wh;
    cudaGetSymbolAddress((void**)&x,    g_x);
    cudaGetSymbolAddress((void**)&qkv,  g_qkv);
    cudaGetSymbolAddress((void**)&pu,   g_pu);
    cudaGetSymbolAddress((void**)&bqkv, g_bqkv);
    cudaGetSymbolAddress((void**)&bpu,  g_bpu);
    cudaGetSymbolAddress((void**)&h,    g_h);
    cudaGetSymbolAddress((void**)&att,  g_att);
    cudaGetSymbolAddress((void**)&gate, g_gate);
    cudaGetSymbolAddress((void**)&wh,   g_wh);

    cudaFuncSetAttribute(gemm_f16_kernel<false>,
                         cudaFuncAttributeMaxDynamicSharedMemorySize, kGemmSmem);
    cudaFuncSetAttribute(gemm_f16_kernel<true>,
                         cudaFuncAttributeMaxDynamicSharedMemorySize, kGemmSmem);

    // streaming weight convert into natural [K][N] fused layouts (8 launches)
    launch_cvt_s(Wq,    wh + qkvOff(0), kD,  kD,  kQS, 0,        kNL, kDD,     3 * kDD);
    launch_cvt_s(Wk,    wh + qkvOff(0), kD,  kD,  kQS, kD,       kNL, kDD,     3 * kDD);
    launch_cvt_s(Wv,    wh + qkvOff(0), kD,  kD,  kQS, 2 * kD,   kNL, kDD,     3 * kDD);
    launch_cvt_s(Wo,    wh + kWoBase,   kD,  kD,  kD,  0,        kNL, kDD,     kDD);
    launch_cvt_s(Wproj, wh + kPuBase,   kD,  kD2, kPU, 0,        kNL, 2 * kDD, 4 * kDD);
    launch_cvt_s(Wup,   wh + kPuBase,   kD,  kD2, kPU, kD2,      kNL, 2 * kDD, 4 * kDD);
    launch_cvt_s(Wdown, wh + kDnBase,   kD2, kD,  kD,  0,        kNL, 2 * kDD, 2 * kDD);
    launch_cvt_s(Wlog,  wh + kLgBase,   kD,  kV,  kV,  0,        1,   0,       0);

    catbias3_kernel<<<dim3(kQS / 256, kNL), 256>>>(bq, bk, bv, bqkv);
    catbias2_kernel<<<dim3(kPU / 256, kNL), 256>>>(bproj, bup, bpu);

    embed_pe_kernel<<<kBL, 256>>>(ids, embed, x);

    for (int i = 0; i < kNL; ++i) {
        rmsnorm_kernel<<<kBL, 256>>>(x, gammas + (size_t)(2 * i) * kD, h);
        launch_gemm_h(h, wh + qkvOff(i), bqkv + (size_t)i * kQS, qkv, kBL, kQS, kD);
        flash_attn_f16<<<dim3(kL / 64, kB * kH), 128, kAttnSmem>>>(qkv, att);
        launch_gemm_f(att, wh + woOff(i), bo + (size_t)i * kD, x, x, kBL, kD, kD);
        rmsnorm_kernel<<<kBL, 256>>>(x, gammas + (size_t)(2 * i + 1) * kD, h);
        launch_gemm_h(h, wh + puOff(i), bpu + (size_t)i * kPU, pu, kBL, kPU, kD);
        silu_gate_kernel<<<((size_t)kBL * kD2) / (256 * 4), 256>>>(pu, gate);
        launch_gemm_f(gate, wh + dnOff(i), bdown + (size_t)i * kD, x, x, kBL, kD, kD2);
    }
    int n4 = (kBL * kD) / 4;
    cvt_h_kernel<<<(n4 + 255) / 256, 256>>>(x, h, n4);
    launch_gemm_f(h, wh + kLgBase, blog, nullptr, out, kBL, kV, kD);
}

// round 17
// speedup vs baseline: 1.4972x; 1.0108x over previous
#include <cuda_runtime.h>
#include <cuda_fp16.h>
#include <math.h>
#include <stdint.h>

// ---------------- problem constants ----------------
constexpr int kNL = 4;
constexpr int kD  = 1024;
constexpr int kD2 = 2048;
constexpr int kH  = 16;
constexpr int kDH = 64;
constexpr int kV  = 32000;
constexpr int kB  = 2;
constexpr int kL  = 2048;
constexpr int kBL = kB * kL;   // 4096
constexpr int kQS = 3 * kD;    // fused qkv row stride (3072)
constexpr int kPU = 2 * kD2;   // interleaved proj|up width (4096)
#define EPSF 1e-6f

// ---------------- scratch (device globals; no allocation allowed) ----------------
__device__ __align__(1024) float  g_x[kBL * kD];                  // residual (fp32)
__device__ __align__(1024) __half g_qkv[(size_t)kBL * kQS];       // fused q|k|v (fp16)
__device__ __align__(1024) __half g_h[kBL * kD];                  // rmsnorm out / logits A
__device__ __align__(1024) __half g_att[kBL * kD];                // attention out
__device__ __align__(1024) __half g_gate[(size_t)kBL * kD2];      // silu out
__device__ __align__(1024) float  g_bqkv[kNL * kQS];              // fused qkv bias
__device__ __align__(1024) float  g_bpu[kNL * kPU];               // interleaved proj/up bias

// fp16 weights in NATURAL [K][N] layout. proj/up interleaved along N.
constexpr size_t kDD = (size_t)kD * kD;                 // 1M
__device__ __forceinline__ __host__ size_t qkvOff(int i) { return (size_t)i * 3 * kDD; }
constexpr size_t kWoBase = (size_t)kNL * 3 * kDD;       // 12M
__device__ __forceinline__ __host__ size_t woOff(int i)  { return kWoBase + (size_t)i * kDD; }
constexpr size_t kPuBase = kWoBase + (size_t)kNL * kDD; // 16M
__device__ __forceinline__ __host__ size_t puOff(int i)  { return kPuBase + (size_t)i * 4 * kDD; }
constexpr size_t kDnBase = kPuBase + (size_t)kNL * 4 * kDD; // 32M
__device__ __forceinline__ __host__ size_t dnOff(int i)  { return kDnBase + (size_t)i * 2 * kDD; }
constexpr size_t kLgBase = kDnBase + (size_t)kNL * 2 * kDD; // 40M
constexpr size_t kWTot = kLgBase + (size_t)kD * kV;         // 72.768M
__device__ __align__(1024) __half g_wh[kWTot];

// ---------------- small helpers ----------------
__device__ __forceinline__ void mma_f16(float* c, const uint32_t* a, uint32_t b0, uint32_t b1) {
    asm volatile(
        "mma.sync.aligned.m16n8k16.row.col.f32.f16.f16.f32 "
        "{%0,%1,%2,%3}, {%4,%5,%6,%7}, {%8,%9}, {%0,%1,%2,%3};"
        : "+f"(c[0]), "+f"(c[1]), "+f"(c[2]), "+f"(c[3])
        : "r"(a[0]), "r"(a[1]), "r"(a[2]), "r"(a[3]), "r"(b0), "r"(b1));
}
__device__ __forceinline__ void cp16(uint32_t dst, const void* src) {
    asm volatile("cp.async.cg.shared.global [%0], [%1], 16;" :: "r"(dst), "l"(src));
}
__device__ __forceinline__ void ldsm4(uint32_t& r0, uint32_t& r1, uint32_t& r2, uint32_t& r3,
                                      uint32_t addr) {
    asm volatile("ldmatrix.sync.aligned.m8n8.x4.shared.b16 {%0,%1,%2,%3}, [%4];"
                 : "=r"(r0), "=r"(r1), "=r"(r2), "=r"(r3) : "r"(addr));
}
__device__ __forceinline__ void ldsm4t(uint32_t& r0, uint32_t& r1, uint32_t& r2, uint32_t& r3,
                                       uint32_t addr) {
    asm volatile("ldmatrix.sync.aligned.m8n8.x4.trans.shared.b16 {%0,%1,%2,%3}, [%4];"
                 : "=r"(r0), "=r"(r1), "=r"(r2), "=r"(r3) : "r"(addr));
}

// ---------------- streaming fp32 -> fp16 weight convert (no transpose) ----------------
__global__ void cvt_s_kernel(const float* __restrict__ in, __half* __restrict__ out,
                             int N, int dstStride, int colOff,
                             size_t srcLayer, size_t dstLayer, int n4)
{
    int i = blockIdx.x * blockDim.x + threadIdx.x;
    if (i >= n4) return;
    in  += (size_t)blockIdx.z * srcLayer;
    out += (size_t)blockIdx.z * dstLayer;
    float4 v = ((const float4*)in)[i];
    int nv = N >> 2;
    int row = i / nv, cv = i - row * nv;
    __half2* op = (__half2*)(out + (size_t)row * dstStride + colOff + cv * 4);
    op[0] = __floats2half2_rn(v.x, v.y);
    op[1] = __floats2half2_rn(v.z, v.w);
}

// ---------------- interleaving proj/up weight convert ----------------
// proj[K][2048], up[K][2048] -> out[K][4096]: col 2j = proj_j, 2j+1 = up_j.
__global__ void cvt_pu_kernel(const float* __restrict__ proj, const float* __restrict__ up,
                              __half* __restrict__ out, int n4)
{
    int i = blockIdx.x * blockDim.x + threadIdx.x;
    if (i >= n4) return;
    proj += (size_t)blockIdx.z * 2 * kDD;
    up   += (size_t)blockIdx.z * 2 * kDD;
    out  += (size_t)blockIdx.z * 4 * kDD;
    float4 p = ((const float4*)proj)[i];
    float4 u = ((const float4*)up)[i];
    int nv = kD2 >> 2;
    int row = i / nv, cv = i - row * nv;
    __half2* op = (__half2*)(out + (size_t)row * kPU + cv * 8);
    op[0] = __floats2half2_rn(p.x, u.x);
    op[1] = __floats2half2_rn(p.y, u.y);
    op[2] = __floats2half2_rn(p.z, u.z);
    op[3] = __floats2half2_rn(p.w, u.w);
}

// ---------------- fp32 -> fp16 convert (logits activations) ----------------
__global__ void cvt_h_kernel(const float* __restrict__ in,
                             __half* __restrict__ out, int n4)
{
    int i = blockIdx.x * blockDim.x + threadIdx.x;
    if (i >= n4) return;
    float4 v = ((const float4*)in)[i];
    __half2* op = (__half2*)(out + (size_t)i * 4);
    op[0] = __floats2half2_rn(v.x, v.y);
    op[1] = __floats2half2_rn(v.z, v.w);
}

// ---------------- bias concat / interleave kernels ----------------
__global__ void catbias3_kernel(const float* __restrict__ a, const float* __restrict__ b,
                                const float* __restrict__ c, float* __restrict__ o)
{
    int l = blockIdx.y;
    int i = blockIdx.x * 256 + threadIdx.x;
    float v;
    if (i < kD)           v = a[l * kD + i];
    else if (i < 2 * kD)  v = b[l * kD + i - kD];
    else                  v = c[l * kD + i - 2 * kD];
    o[(size_t)l * kQS + i] = v;
}
__global__ void ilvbias2_kernel(const float* __restrict__ a, const float* __restrict__ b,
                                float* __restrict__ o)
{
    int l = blockIdx.y;
    int i = blockIdx.x * 256 + threadIdx.x;   // 0..2*kD2-1 (interleaved index)
    int j = i >> 1;
    float v = (i & 1) ? b[l * kD2 + j] : a[l * kD2 + j];
    o[(size_t)l * kPU + i] = v;
}

// ---------------- embed + positional encoding ----------------
__global__ void embed_pe_kernel(const int* __restrict__ ids,
                                const float* __restrict__ embed,
                                float* __restrict__ x)
{
    int row = blockIdx.x;
    int l   = row % kL;
    int id  = ids[row];
    int d0  = threadIdx.x * 4;
    float4 ev = *(const float4*)&embed[(size_t)id * kD + d0];
    float out[4] = {ev.x, ev.y, ev.z, ev.w};
    const float negc = -0.0089944731f;   // -log(10000)/1024 in fp32
#pragma unroll
    for (int t = 0; t < 4; ++t) {
        int d  = d0 + t;
        int i2 = (d >> 1) * 2;
        float freq = expf((float)i2 * negc);
        float a    = (float)l * freq;
        out[t] += (d & 1) ? cosf(a) : sinf(a);
    }
    *(float4*)&x[(size_t)row * kD + d0] = make_float4(out[0], out[1], out[2], out[3]);
}

// ---------------- rmsnorm (emits fp16) ----------------
__global__ void rmsnorm_kernel(const float* __restrict__ x,
                               const float* __restrict__ gamma,
                               __half* __restrict__ y)
{
    int row = blockIdx.x;
    const float* xr = x + (size_t)row * kD;
    int d0 = threadIdx.x * 4;
    float4 v = *(const float4*)&xr[d0];
    float ss = v.x * v.x + v.y * v.y + v.z * v.z + v.w * v.w;
#pragma unroll
    for (int off = 16; off; off >>= 1)
        ss += __shfl_xor_sync(0xffffffffu, ss, off);
    __shared__ float ws[8];
    int lane = threadIdx.x & 31, w = threadIdx.x >> 5;
    if (lane == 0) ws[w] = ss;
    __syncthreads();
    if (w == 0) {
        float t = (lane < 8) ? ws[lane] : 0.0f;
#pragma unroll
        for (int off = 4; off; off >>= 1)
            t += __shfl_xor_sync(0xffffffffu, t, off);
        if (lane == 0) ws[0] = t;
    }
    __syncthreads();
    float scale = rsqrtf(ws[0] / (float)kD + EPSF);
    float4 g = *(const float4*)&gamma[d0];
    __half2* yp = (__half2*)&y[(size_t)row * kD + d0];
    yp[0] = __floats2half2_rn(v.x * scale * g.x, v.y * scale * g.y);
    yp[1] = __floats2half2_rn(v.z * scale * g.z, v.w * scale * g.w);
}

// ================= FP16 GEMM: K-64 chunks, B natural [K][N], ldsm.trans =================
// Output modes: 0 = fp32 (+resid), 1 = fp16, 2 = silu-gate (interleaved proj/up -> N/2 fp16)
constexpr int kABytes = 128 * 72 * 2;      // 18432 B
constexpr int kBBytes = 64 * 136 * 2;      // 17408 B
constexpr int kBufBytes = kABytes + kBBytes;  // 35840 per stage
constexpr int kGemmSmem = 3 * kBufBytes;      // 107520

template<int OMODE>
__global__ void __launch_bounds__(256, 2)
gemm_f16_kernel(const __half* __restrict__ A, const __half* __restrict__ Bw,
                const float* __restrict__ bias, const float* __restrict__ resid,
                void* __restrict__ Cv, int M, int N, int K)
{
    extern __shared__ char smem[];
    uint32_t base = (uint32_t)__cvta_generic_to_shared(smem);

    int tid  = threadIdx.x;
    int lane = tid & 31;
    int warp = tid >> 5;
    int wm = warp >> 2;
    int wn = warp & 3;
    int bm = blockIdx.y, bn = blockIdx.x;

    const __half* Ab = A  + (size_t)bm * 128 * K;
    const __half* Bb = Bw + (size_t)(bn * 128);

    int arw[4], asb[4], brw[4], bsb[4];
    uint32_t dstA[4], dstB[4];
#pragma unroll
    for (int i = 0; i < 4; ++i) {
        int c = i * 256 + tid;
        arw[i] = c >> 3;  asb[i] = c & 7;
        dstA[i] = base + (uint32_t)(arw[i] * 144 + asb[i] * 16);
        brw[i] = c >> 4;  bsb[i] = c & 15;
        dstB[i] = base + (uint32_t)(kABytes + brw[i] * 272 + bsb[i] * 16);
    }

    int q  = lane >> 3;
    int r8 = lane & 7;
    uint32_t aAddr = base + (uint32_t)((wm * 64 + (q & 1) * 8 + r8) * 144 + (q >> 1) * 16);
    uint32_t bAddr = base + (uint32_t)(kABytes + ((q & 1) * 8 + r8) * 272
                                       + (wn * 32 + (q >> 1) * 8) * 2);

    float acc[4][4][4];
#pragma unroll
    for (int mt = 0; mt < 4; ++mt)
#pragma unroll
        for (int nt = 0; nt < 4; ++nt)
#pragma unroll
            for (int r = 0; r < 4; ++r) acc[mt][nt][r] = 0.0f;

    int nit = K >> 6;

    auto stage = [&](int k0, int b) {
        uint32_t boff = (uint32_t)(b * kBufBytes);
#pragma unroll
        for (int i = 0; i < 4; ++i) {
            cp16(dstA[i] + boff, &Ab[(size_t)arw[i] * K + k0 + asb[i] * 8]);
            cp16(dstB[i] + boff, &Bb[(size_t)(k0 + brw[i]) * N + bsb[i] * 8]);
        }
        asm volatile("cp.async.commit_group;");
    };

    stage(0, 0);
    if (nit > 1) stage(64, 1);

    int buf = 0;
    for (int it = 0; it < nit; ++it) {
        if (it + 1 < nit) asm volatile("cp.async.wait_group 1;");
        else              asm volatile("cp.async.wait_group 0;");
        __syncthreads();
        if (it + 2 < nit) {
            int nb = buf + 2; if (nb >= 3) nb -= 3;
            stage((it + 2) << 6, nb);
        }
        uint32_t bufoff = (uint32_t)(buf * kBufBytes);
#pragma unroll
        for (int ks = 0; ks < 4; ++ks) {
            uint32_t afr[4][4], bfr[4][2];
#pragma unroll
            for (int mt = 0; mt < 4; ++mt)
                ldsm4(afr[mt][0], afr[mt][1], afr[mt][2], afr[mt][3],
                      aAddr + bufoff + (uint32_t)(ks * 32 + mt * 16 * 144));
#pragma unroll
            for (int np = 0; np < 2; ++np) {
                uint32_t r0, r1, r2, r3;
                ldsm4t(r0, r1, r2, r3,
                       bAddr + bufoff + (uint32_t)(ks * 16 * 272 + np * 32));
                bfr[2 * np][0] = r0; bfr[2 * np][1] = r1;
                bfr[2 * np + 1][0] = r2; bfr[2 * np + 1][1] = r3;
            }
#pragma unroll
            for (int mt = 0; mt < 4; ++mt)
#pragma unroll
                for (int nt = 0; nt < 4; ++nt)
                    mma_f16(acc[mt][nt], afr[mt], bfr[nt][0], bfr[nt][1]);
        }
        if (++buf == 3) buf = 0;
    }

    int rb = bm * 128 + wm * 64 + (lane >> 2);
    int cb = bn * 128 + wn * 32 + (lane & 3) * 2;
#pragma unroll
    for (int mt = 0; mt < 4; ++mt) {
#pragma unroll
        for (int nt = 0; nt < 4; ++nt) {
            int r0 = rb + mt * 16;
            int c0 = cb + nt * 8;
            float b0 = bias[c0], b1 = bias[c0 + 1];
            float v0 = acc[mt][nt][0] + b0, v1 = acc[mt][nt][1] + b1;
            float v2 = acc[mt][nt][2] + b0, v3 = acc[mt][nt][3] + b1;
            if (OMODE == 0) {
                size_t off0 = (size_t)r0 * N + c0;
                size_t off1 = (size_t)(r0 + 8) * N + c0;
                float* C = (float*)Cv;
                if (resid) {
                    float2 rr0 = *(const float2*)&resid[off0];
                    float2 rr1 = *(const float2*)&resid[off1];
                    v0 += rr0.x; v1 += rr0.y; v2 += rr1.x; v3 += rr1.y;
                }
                *(float2*)&C[off0] = make_float2(v0, v1);
                *(float2*)&C[off1] = make_float2(v2, v3);
            } else if (OMODE == 1) {
                size_t off0 = (size_t)r0 * N + c0;
                size_t off1 = (size_t)(r0 + 8) * N + c0;
                __half* C = (__half*)Cv;
                *(__half2*)&C[off0] = __floats2half2_rn(v0, v1);
                *(__half2*)&C[off1] = __floats2half2_rn(v2, v3);
            } else {
                // silu gate: (v0,v1)=(proj,up) for logical col c0/2
                int gc = c0 >> 1;
                int gw = N >> 1;
                float t0 = v0 * v1, t1 = v2 * v3;
                float s0 = t0 / (1.0f + __expf(-t0));
                float s1 = t1 / (1.0f + __expf(-t1));
                __half* C = (__half*)Cv;
                C[(size_t)r0 * gw + gc]       = __float2half_rn(s0);
                C[(size_t)(r0 + 8) * gw + gc] = __float2half_rn(s1);
            }
        }
    }
}

// ================= flash attention, FP16 MMA end-to-end (R13, unchanged) =================
constexpr int kKVp = 72;
constexpr int kAttnSmem = (2 * 64 * kKVp + 4 * 16 * kKVp) * 2;  // 27648 B

__global__ void __launch_bounds__(128)
flash_attn_f16(const __half* __restrict__ QKV, __half* __restrict__ O)
{
    extern __shared__ __half hsm[];
    __half* Ks = hsm;
    __half* Vs = hsm + 64 * kKVp;
    __half* Ps = hsm + 2 * 64 * kKVp + (threadIdx.x >> 5) * 16 * kKVp;
    uint32_t ksBase = (uint32_t)__cvta_generic_to_shared(Ks);
    uint32_t vsBase = (uint32_t)__cvta_generic_to_shared(Vs);

    int tid = threadIdx.x, lane = tid & 31, w = tid >> 5;
    int g = lane >> 2, tg = lane & 3;
    int q  = lane >> 3;
    int r8 = lane & 7;
    int bh = blockIdx.y;
    int b  = bh >> 4;
    int h  = bh & 15;
    int q0 = blockIdx.x * 64;
    size_t baseq = ((size_t)b * kL) * kQS + (size_t)h * kDH;
    size_t obase = ((size_t)b * kL) * kD  + (size_t)h * kDH;
    int rlo = q0 + w * 16 + g;

    uint32_t kAddr = ksBase + (uint32_t)((((q & 1) * 8 + r8) * kKVp + (q >> 1) * 8) * 2);
    uint32_t vAddr = vsBase + (uint32_t)((((q & 1) * 8 + r8) * kKVp + (q >> 1) * 8) * 2);

    uint32_t qf[4][4];
    {
        const __half* Qp = QKV + baseq + (size_t)rlo * kQS;
#pragma unroll
        for (int ks = 0; ks < 4; ++ks) {
            int kk = ks * 16 + 2 * tg;
            qf[ks][0] = *(const uint32_t*)&Qp[kk];
            qf[ks][1] = *(const uint32_t*)&Qp[(size_t)8 * kQS + kk];
            qf[ks][2] = *(const uint32_t*)&Qp[kk + 8];
            qf[ks][3] = *(const uint32_t*)&Qp[(size_t)8 * kQS + kk + 8];
        }
    }

    float of[8][4];
#pragma unroll
    for (int nt = 0; nt < 8; ++nt)
#pragma unroll
        for (int e = 0; e < 4; ++e) of[nt][e] = 0.0f;
    float mlo = -1e30f, mhi = -1e30f, llo = 0.0f, lhi = 0.0f;

    int nkt = blockIdx.x + 1;
    for (int kt = 0; kt < nkt; ++kt) {
        int k0 = kt * 64;
        __syncthreads();
#pragma unroll
        for (int i = 0; i < 4; ++i) {
            int c = i * 128 + tid;
            int row = c >> 3;
            int h8  = (c & 7) * 8;
            size_t roff = baseq + (size_t)(k0 + row) * kQS + h8;
            *(uint4*)&Ks[row * kKVp + h8] = *(const uint4*)&QKV[roff + kD];
            *(uint4*)&Vs[row * kKVp + h8] = *(const uint4*)&QKV[roff + 2 * kD];
        }
        __syncthreads();

        float s[8][4];
#pragma unroll
        for (int nt = 0; nt < 8; ++nt)
#pragma unroll
            for (int e = 0; e < 4; ++e) s[nt][e] = 0.0f;
#pragma unroll
        for (int ks = 0; ks < 4; ++ks) {
            uint32_t bfr[8][2];
#pragma unroll
            for (int np = 0; np < 4; ++np) {
                uint32_t r0, r1, r2, r3;
                ldsm4(r0, r1, r2, r3,
                      kAddr + (uint32_t)(((np * 16) * kKVp + ks * 16) * 2));
                bfr[2 * np][0] = r0; bfr[2 * np + 1][0] = r1;
                bfr[2 * np][1] = r2; bfr[2 * np + 1][1] = r3;
            }
#pragma unroll
            for (int nt = 0; nt < 8; ++nt)
                mma_f16(s[nt], qf[ks], bfr[nt][0], bfr[nt][1]);
        }

        bool diag = (kt == blockIdx.x);
        float rmlo = -1e30f, rmhi = -1e30f;
#pragma unroll
        for (int nt = 0; nt < 8; ++nt) {
#pragma unroll
            for (int e = 0; e < 4; ++e) {
                float v = s[nt][e] * 0.125f;
                if (diag) {
                    int key = k0 + nt * 8 + 2 * tg + (e & 1);
                    int row = (e < 2) ? rlo : rlo + 8;
                    if (key > row) v = -1e30f;
                }
                s[nt][e] = v;
                if (e < 2) rmlo = fmaxf(rmlo, v); else rmhi = fmaxf(rmhi, v);
            }
        }
        rmlo = fmaxf(rmlo, __shfl_xor_sync(0xffffffffu, rmlo, 1));
        rmlo = fmaxf(rmlo, __shfl_xor_sync(0xffffffffu, rmlo, 2));
        rmhi = fmaxf(rmhi, __shfl_xor_sync(0xffffffffu, rmhi, 1));
        rmhi = fmaxf(rmhi, __shfl_xor_sync(0xffffffffu, rmhi, 2));
        float mnlo = fmaxf(mlo, rmlo), mnhi = fmaxf(mhi, rmhi);
        float clo = __expf(mlo - mnlo), chi = __expf(mhi - mnhi);
        mlo = mnlo; mhi = mnhi;

        float rslo = 0.0f, rshi = 0.0f;
#pragma unroll
        for (int nt = 0; nt < 8; ++nt) {
            float p0 = __expf(s[nt][0] - mlo);
            float p1 = __expf(s[nt][1] - mlo);
            float p2 = __expf(s[nt][2] - mhi);
            float p3 = __expf(s[nt][3] - mhi);
            rslo += p0 + p1; rshi += p2 + p3;
            int col = nt * 8 + 2 * tg;
            *(__half2*)&Ps[g * kKVp + col]       = __floats2half2_rn(p0, p1);
            *(__half2*)&Ps[(g + 8) * kKVp + col] = __floats2half2_rn(p2, p3);
        }
        rslo += __shfl_xor_sync(0xffffffffu, rslo, 1);
        rslo += __shfl_xor_sync(0xffffffffu, rslo, 2);
        rshi += __shfl_xor_sync(0xffffffffu, rshi, 1);
        rshi += __shfl_xor_sync(0xffffffffu, rshi, 2);
        llo = llo * clo + rslo;
        lhi = lhi * chi + rshi;
#pragma unroll
        for (int nt = 0; nt < 8; ++nt) {
            of[nt][0] *= clo; of[nt][1] *= clo;
            of[nt][2] *= chi; of[nt][3] *= chi;
        }
        __syncwarp();

#pragma unroll
        for (int ks = 0; ks < 4; ++ks) {
            int kk = ks * 16;
            uint32_t pa[4];
            pa[0] = *(const uint32_t*)&Ps[g * kKVp + kk + 2 * tg];
            pa[1] = *(const uint32_t*)&Ps[(g + 8) * kKVp + kk + 2 * tg];
            pa[2] = *(const uint32_t*)&Ps[g * kKVp + kk + 8 + 2 * tg];
            pa[3] = *(const uint32_t*)&Ps[(g + 8) * kKVp + kk + 8 + 2 * tg];
            uint32_t bfr[8][2];
#pragma unroll
            for (int np = 0; np < 4; ++np) {
                uint32_t r0, r1, r2, r3;
                ldsm4t(r0, r1, r2, r3,
                       vAddr + (uint32_t)((kk * kKVp + np * 16) * 2));
                bfr[2 * np][0] = r0; bfr[2 * np][1] = r1;
                bfr[2 * np + 1][0] = r2; bfr[2 * np + 1][1] = r3;
            }
#pragma unroll
            for (int nt = 0; nt < 8; ++nt)
                mma_f16(of[nt], pa, bfr[nt][0], bfr[nt][1]);
        }
        __syncwarp();
    }

    float ilo = 1.0f / llo, ihi = 1.0f / lhi;
#pragma unroll
    for (int nt = 0; nt < 8; ++nt) {
        int col = nt * 8 + 2 * tg;
        size_t off0 = obase + (size_t)rlo * kD + col;
        size_t off1 = obase + (size_t)(rlo + 8) * kD + col;
        *(__half2*)&O[off0] = __floats2half2_rn(of[nt][0] * ilo, of[nt][1] * ilo);
        *(__half2*)&O[off1] = __floats2half2_rn(of[nt][2] * ihi, of[nt][3] * ihi);
    }
}

// ---------------- host launcher ----------------
static void launch_gemm_f(const __half* A, const __half* Bw, const float* bias,
                          const float* resid, float* C, int M, int N, int K)
{
    dim3 grid(N / 128, M / 128);
    gemm_f16_kernel<0><<<grid, 256, kGemmSmem>>>(A, Bw, bias, resid, C, M, N, K);
}
static void launch_gemm_h(const __half* A, const __half* Bw, const float* bias,
                          __half* C, int M, int N, int K)
{
    dim3 grid(N / 128, M / 128);
    gemm_f16_kernel<1><<<grid, 256, kGemmSmem>>>(A, Bw, bias, nullptr, C, M, N, K);
}
static void launch_gemm_g(const __half* A, const __half* Bw, const float* bias,
                          __half* C, int M, int N, int K)
{
    dim3 grid(N / 128, M / 128);
    gemm_f16_kernel<2><<<grid, 256, kGemmSmem>>>(A, Bw, bias, nullptr, C, M, N, K);
}
static void launch_cvt_s(const float* in, __half* out, int K, int N,
                         int dstStride, int colOff, int layers,
                         size_t srcLayer, size_t dstLayer)
{
    int n4 = (K * N) / 4;
    dim3 grid((n4 + 255) / 256, 1, layers);
    cvt_s_kernel<<<grid, 256>>>(in, out, N, dstStride, colOff, srcLayer, dstLayer, n4);
}

extern "C" void kernel_launch(void* const* d_in, const int* in_sizes, int n_in,
                              void* d_out, int out_size)
{
    const int*   ids    = (const int*)  d_in[0];
    const float* embed  = (const float*)d_in[1];
    const float* Wq     = (const float*)d_in[2];
    const float* bq     = (const float*)d_in[3];
    const float* Wk     = (const float*)d_in[4];
    const float* bk     = (const float*)d_in[5];
    const float* Wv     = (const float*)d_in[6];
    const float* bv     = (const float*)d_in[7];
    const float* Wo     = (const float*)d_in[8];
    const float* bo     = (const float*)d_in[9];
    const float* Wproj  = (const float*)d_in[10];
    const float* bproj  = (const float*)d_in[11];
    const float* Wup    = (const float*)d_in[12];
    const float* bup    = (const float*)d_in[13];
    const float* Wdown  = (const float*)d_in[14];
    const float* bdown  = (const float*)d_in[15];
    const float* gammas = (const float*)d_in[16];
    const float* Wlog   = (const float*)d_in[17];
    const float* blog   = (const float*)d_in[18];
    float* out = (float*)d_out;

    float *x, *bqkv, *bpu;
    __half *qkv, *h, *att, *gate, *wh;
    cudaGetSymbolAddress((void**)&x,    g_x);
    cudaGetSymbolAddress((void**)&qkv,  g_qkv);
    cudaGetSymbolAddress((void**)&bqkv, g_bqkv);
    cudaGetSymbolAddress((void**)&bpu,  g_bpu);
    cudaGetSymbolAddress((void**)&h,    g_h);
    cudaGetSymbolAddress((void**)&att,  g_att);
    cudaGetSymbolAddress((void**)&gate, g_gate);
    cudaGetSymbolAddress((void**)&wh,   g_wh);

    cudaFuncSetAttribute(gemm_f16_kernel<0>,
                         cudaFuncAttributeMaxDynamicSharedMemorySize, kGemmSmem);
    cudaFuncSetAttribute(gemm_f16_kernel<1>,
                         cudaFuncAttributeMaxDynamicSharedMemorySize, kGemmSmem);
    cudaFuncSetAttribute(gemm_f16_kernel<2>,
                         cudaFuncAttributeMaxDynamicSharedMemorySize, kGemmSmem);

    // streaming weight convert into natural [K][N] fused layouts
    launch_cvt_s(Wq,    wh + qkvOff(0), kD,  kD,  kQS, 0,        kNL, kDD,     3 * kDD);
    launch_cvt_s(Wk,    wh + qkvOff(0), kD,  kD,  kQS, kD,       kNL, kDD,     3 * kDD);
    launch_cvt_s(Wv,    wh + qkvOff(0), kD,  kD,  kQS, 2 * kD,   kNL, kDD,     3 * kDD);
    launch_cvt_s(Wo,    wh + kWoBase,   kD,  kD,  kD,  0,        kNL, kDD,     kDD);
    {   // interleaved proj/up
        int n4 = (kD * kD2) / 4;
        dim3 grid((n4 + 255) / 256, 1, kNL);
        cvt_pu_kernel<<<grid, 256>>>(Wproj, Wup, wh + kPuBase, n4);
    }
    launch_cvt_s(Wdown, wh + kDnBase,   kD2, kD,  kD,  0,        kNL, 2 * kDD, 2 * kDD);
    launch_cvt_s(Wlog,  wh + kLgBase,   kD,  kV,  kV,  0,        1,   0,       0);

    catbias3_kernel<<<dim3(kQS / 256, kNL), 256>>>(bq, bk, bv, bqkv);
    ilvbias2_kernel<<<dim3(kPU / 256, kNL), 256>>>(bproj, bup, bpu);

    embed_pe_kernel<<<kBL, 256>>>(ids, embed, x);

    for (int i = 0; i < kNL; ++i) {
        rmsnorm_kernel<<<kBL, 256>>>(x, gammas + (size_t)(2 * i) * kD, h);
        launch_gemm_h(h, wh + qkvOff(i), bqkv + (size_t)i * kQS, qkv, kBL, kQS, kD);
        flash_attn_f16<<<dim3(kL / 64, kB * kH), 128, kAttnSmem>>>(qkv, att);
        launch_gemm_f(att, wh + woOff(i), bo + (size_t)i * kD, x, x, kBL, kD, kD);
        rmsnorm_kernel<<<kBL, 256>>>(x, gammas + (size_t)(2 * i + 1) * kD, h);
        launch_gemm_g(h, wh + puOff(i), bpu + (size_t)i * kPU, gate, kBL, kPU, kD);
        launch_gemm_f(gate, wh + dnOff(i), bdown + (size_t)i * kD, x, x, kBL, kD, kD2);
    }
    int n4 = (kBL * kD) / 4;
    cvt_h_kernel<<<(n4 + 255) / 256, 256>>>(x, h, n4);
    launch_gemm_f(h, wh + kLgBase, blog, nullptr, out, kBL, kV, kD);
}